// round 11
// baseline (speedup 1.0000x reference)
#include <cuda_runtime.h>
#include <cuda_bf16.h>
#include <cuda_fp16.h>
#include <math.h>
#include <stdint.h>

// Problem constants
#define BTN   128
#define SEQ   256
#define DIM   1024
#define NH    16
#define NKV   4
#define GRP   4
#define HD    64
#define MROWS (BTN*SEQ)      // 32768
#define QKVC  1536
#define GK    1024
#define EPSV  1e-6f
#define SCALEV 0.125f
#define CAPV  50.0f

// ---------------------------------------------------------------------------
// Scratch (device globals)
// ---------------------------------------------------------------------------
__device__ __align__(16) __half g_x16[(size_t)MROWS * GK];        // x as fp16
__device__ __align__(16) __half g_a16[(size_t)MROWS * GK];        // attn out fp16
__device__ __align__(16) __half g_w1h[(size_t)QKVC * GK];         // [n][k] hi
__device__ __align__(16) __half g_w1l[(size_t)QKVC * GK];         // [n][k] lo
__device__ __align__(16) __half g_w2h[(size_t)DIM * GK];
__device__ __align__(16) __half g_w2l[(size_t)DIM * GK];
// attention tiles (bf16 hi/lo)
__device__ __align__(16) __nv_bfloat16 g_qth[(size_t)MROWS * GK];
__device__ __align__(16) __nv_bfloat16 g_qtl[(size_t)MROWS * GK];
__device__ __align__(16) __nv_bfloat16 g_kh[(size_t)MROWS * 256];
__device__ __align__(16) __nv_bfloat16 g_kl[(size_t)MROWS * 256];
__device__ __align__(16) __nv_bfloat16 g_vh[(size_t)MROWS * 256];
__device__ __align__(16) __nv_bfloat16 g_vl[(size_t)MROWS * 256];

// ---------------------------------------------------------------------------
// helpers
// ---------------------------------------------------------------------------
__device__ __forceinline__ uint32_t smem_u32(const void* p) {
    uint32_t a;
    asm("{ .reg .u64 t; cvta.to.shared.u64 t, %1; cvt.u32.u64 %0, t; }"
        : "=r"(a) : "l"(p));
    return a;
}
__device__ __forceinline__ void cp16(uint32_t dst, const void* src) {
    asm volatile("cp.async.cg.shared.global [%0], [%1], 16;" :: "r"(dst), "l"(src));
}
__device__ __forceinline__ void ldmx4(uint32_t r[4], uint32_t addr) {
    asm volatile("ldmatrix.sync.aligned.m8n8.x4.shared.b16 {%0,%1,%2,%3}, [%4];"
                 : "=r"(r[0]), "=r"(r[1]), "=r"(r[2]), "=r"(r[3]) : "r"(addr));
}
__device__ __forceinline__ void ldmx4t(uint32_t r[4], uint32_t addr) {
    asm volatile("ldmatrix.sync.aligned.m8n8.x4.trans.shared.b16 {%0,%1,%2,%3}, [%4];"
                 : "=r"(r[0]), "=r"(r[1]), "=r"(r[2]), "=r"(r[3]) : "r"(addr));
}
__device__ __forceinline__ void mma_bf(float c[4], const uint32_t a[4],
                                       const uint32_t b[2]) {
    asm volatile("mma.sync.aligned.m16n8k16.row.col.f32.bf16.bf16.f32 "
                 "{%0,%1,%2,%3}, {%4,%5,%6,%7}, {%8,%9}, {%0,%1,%2,%3};"
                 : "+f"(c[0]), "+f"(c[1]), "+f"(c[2]), "+f"(c[3])
                 : "r"(a[0]), "r"(a[1]), "r"(a[2]), "r"(a[3]),
                   "r"(b[0]), "r"(b[1]));
}
__device__ __forceinline__ void mma_fp(float c[4], const uint32_t a[4],
                                       const uint32_t b[2]) {
    asm volatile("mma.sync.aligned.m16n8k16.row.col.f32.f16.f16.f32 "
                 "{%0,%1,%2,%3}, {%4,%5,%6,%7}, {%8,%9}, {%0,%1,%2,%3};"
                 : "+f"(c[0]), "+f"(c[1]), "+f"(c[2]), "+f"(c[3])
                 : "r"(a[0]), "r"(a[1]), "r"(a[2]), "r"(a[3]),
                   "r"(b[0]), "r"(b[1]));
}
__device__ __forceinline__ void split2(float a, float b, uint32_t& H, uint32_t& L) {
    __nv_bfloat16 ah = __float2bfloat16(a), bh = __float2bfloat16(b);
    __nv_bfloat162 hh(ah, bh);
    H = *(uint32_t*)&hh;
    __nv_bfloat162 ll(__float2bfloat16(a - __bfloat162float(ah)),
                      __float2bfloat16(b - __bfloat162float(bh)));
    L = *(uint32_t*)&ll;
}
#define ASW(o) ((o) ^ (((o) >> 3) & 0x70))

// ---------------------------------------------------------------------------
// conversions
// ---------------------------------------------------------------------------
__global__ void cvt_half(const float* __restrict__ in,
                         __half* __restrict__ out, int n4)
{
    int i = blockIdx.x * blockDim.x + threadIdx.x;
    if (i >= n4) return;
    float4 v = ((const float4*)in)[i];
    __half2* op = (__half2*)out;
    op[2*i]   = __floats2half2_rn(v.x, v.y);
    op[2*i+1] = __floats2half2_rn(v.z, v.w);
}

__global__ void xpose_qkv(const float* __restrict__ Wq, const float* __restrict__ Wk,
                          const float* __restrict__ Wv,
                          __half* __restrict__ th, __half* __restrict__ tl)
{
    size_t idx = (size_t)blockIdx.x * blockDim.x + threadIdx.x;
    if (idx >= (size_t)QKVC * GK) return;
    int k = (int)(idx & (GK - 1));
    int n = (int)(idx >> 10);
    float v;
    if (n < DIM)            v = Wq[(size_t)k * (NH*HD)  + n];
    else if (n < DIM + 256) v = Wk[(size_t)k * (NKV*HD) + (n - DIM)];
    else                    v = Wv[(size_t)k * (NKV*HD) + (n - DIM - 256)];
    __half hv = __float2half_rn(v);
    th[idx] = hv;
    tl[idx] = __float2half_rn(v - __half2float(hv));
}

__global__ void xpose_wo(const float* __restrict__ W,
                         __half* __restrict__ th, __half* __restrict__ tl)
{
    size_t idx = (size_t)blockIdx.x * blockDim.x + threadIdx.x;
    if (idx >= (size_t)DIM * GK) return;
    int k = (int)(idx & (GK - 1));
    int n = (int)(idx >> 10);
    float v = W[(size_t)k * DIM + n];
    __half hv = __float2half_rn(v);
    th[idx] = hv;
    tl[idx] = __float2half_rn(v - __half2float(hv));
}

// ---------------------------------------------------------------------------
// fp16 2-term GEMM: C[m,n] = A[m,:].(Bh[n,:]+Bl[n,:]),  K=1024
// 128x128 CTA tile, 8 warps in 2m x 4n grid (64x32 warp tiles), BK=64,
// 2-stage, SW128 swizzled smem, 2 CTAs/SM.
// EPI=0: plain fp32 store.  EPI=1: QKV epilogue (rmsnorm fold + bf16 split).
// ---------------------------------------------------------------------------
#define BK      64
#define NCHUNK  (GK / BK)             // 16
#define TILE_B  (128 * 128)           // 16384 (128 rows x 128B)
#define OFF_A   0
#define OFF_BH  TILE_B
#define OFF_BL  (2*TILE_B)
#define STG     (3*TILE_B)            // 49152
#define SMEM_GEMM (2 * STG + 1024)    // 99328

__device__ __forceinline__ void g_load(uint32_t sbase, int tid,
    const __half* A, const __half* Bh, const __half* Bl, int koff)
{
    #pragma unroll
    for (int it = 0; it < 4; it++) {
        int g = tid + it * 256;            // 0..1023 granules per array
        int row = g >> 3;
        int j   = g & 7;
        uint32_t dst = sbase + ASW((uint32_t)(row * 128 + j * 16));
        size_t so = (size_t)row * GK + koff + j * 8;
        cp16(dst + OFF_A,  A  + so);
        cp16(dst + OFF_BH, Bh + so);
        cp16(dst + OFF_BL, Bl + so);
    }
    asm volatile("cp.async.commit_group;" ::: "memory");
}

template<int EPI>
__global__ void __launch_bounds__(256, 2)
gemm_mma(const __half* __restrict__ a, const __half* __restrict__ bh,
         const __half* __restrict__ bl, float* __restrict__ C, int ldc,
         const float* __restrict__ qw, const float* __restrict__ kw)
{
    extern __shared__ char smem_raw[];
    uint32_t sbr = smem_u32(smem_raw);
    const uint32_t sb = (sbr + 1023) & ~1023u;
    const int tid  = threadIdx.x;
    const int wid  = tid >> 5;
    const int lane = tid & 31;
    const int bm = blockIdx.y * 128;
    const int bn = blockIdx.x * 128;

    const __half* A  = a  + (size_t)bm * GK;
    const __half* Bh = bh + (size_t)bn * GK;
    const __half* Bl = bl + (size_t)bn * GK;

    const int wm = (wid & 1) * 64;       // 2 m positions (64 rows each)
    const int wn = (wid >> 1) * 32;      // 4 n positions (32 cols each)
    const int ar = lane & 15;
    const int ac = (lane >> 4) * 16;
    const int br = (lane & 7) + ((lane >> 4) & 1) * 8;
    const int bc = ((lane >> 3) & 1) * 16;

    float acc[4][4][4];
    #pragma unroll
    for (int i = 0; i < 4; i++)
        #pragma unroll
        for (int j = 0; j < 4; j++)
            #pragma unroll
            for (int e = 0; e < 4; e++) acc[i][j][e] = 0.f;

    g_load(sb, tid, A, Bh, Bl, 0);

    for (int c = 0; c < NCHUNK; c++) {
        asm volatile("cp.async.wait_group 0;" ::: "memory");
        __syncthreads();
        if (c + 1 < NCHUNK)
            g_load(sb + ((c + 1) & 1) * STG, tid, A, Bh, Bl, (c + 1) * BK);

        const uint32_t st = sb + (c & 1) * STG;
        #pragma unroll
        for (int kk = 0; kk < 4; kk++) {
            const int kb = kk * 32;      // byte offset of this k16 within 128B row
            uint32_t fA[4][4];
            #pragma unroll
            for (int mt = 0; mt < 4; mt++) {
                uint32_t off = ASW((uint32_t)((wm + mt * 16 + ar) * 128 + kb + ac));
                ldmx4(fA[mt], st + OFF_A + off);
            }
            uint32_t fBh[4][2], fBl[4][2];
            #pragma unroll
            for (int g = 0; g < 2; g++) {
                uint32_t off = ASW((uint32_t)((wn + g * 16 + br) * 128 + kb + bc));
                uint32_t t[4];
                ldmx4(t, st + OFF_BH + off);
                fBh[2*g][0] = t[0]; fBh[2*g][1] = t[1];
                fBh[2*g+1][0] = t[2]; fBh[2*g+1][1] = t[3];
                ldmx4(t, st + OFF_BL + off);
                fBl[2*g][0] = t[0]; fBl[2*g][1] = t[1];
                fBl[2*g+1][0] = t[2]; fBl[2*g+1][1] = t[3];
            }
            #pragma unroll
            for (int mt = 0; mt < 4; mt++)
                #pragma unroll
                for (int nt = 0; nt < 4; nt++) {
                    mma_fp(acc[mt][nt], fA[mt], fBh[nt]);
                    mma_fp(acc[mt][nt], fA[mt], fBl[nt]);
                }
        }
    }

    const int er = lane >> 2;
    const int ec = (lane & 3) * 2;

    if (EPI == 0) {
        #pragma unroll
        for (int mt = 0; mt < 4; mt++)
            #pragma unroll
            for (int nt = 0; nt < 4; nt++) {
                size_t row0 = (size_t)(bm + wm + mt * 16 + er) * ldc
                            + bn + wn + nt * 8 + ec;
                *(float2*)&C[row0]           = make_float2(acc[mt][nt][0], acc[mt][nt][1]);
                *(float2*)&C[row0 + 8 * ldc] = make_float2(acc[mt][nt][2], acc[mt][nt][3]);
            }
        return;
    }

    // ---- EPI == 1: QKV epilogue, rmsnorm spans 2 warps (64-col head) ----
    const int gn = bn + wn;              // 32-aligned; head = 64-aligned pair
    const int ngrp = wid >> 1;           // n-group 0..3
    float* red = (float*)(smem_raw + (sb - sbr));   // [128 rows][4 ngrp]

    float wqk[8];
    if (gn < DIM) {
        #pragma unroll
        for (int nt = 0; nt < 4; nt++) {
            int col = (wn & 32) + nt * 8 + ec;
            wqk[2*nt]   = __ldg(&qw[col])   * __ldg(&kw[col]);
            wqk[2*nt+1] = __ldg(&qw[col+1]) * __ldg(&kw[col+1]);
        }
    }

    __syncthreads();   // all warps done reading stage buffers
    // pass 1: publish 32-col partial ssq per row
    #pragma unroll
    for (int mt = 0; mt < 4; mt++) {
        #pragma unroll
        for (int hf = 0; hf < 2; hf++) {
            const int rowIdx = wm + mt * 16 + er + hf * 8;
            float ssq = 0.f;
            #pragma unroll
            for (int nt = 0; nt < 4; nt++) {
                float v0 = acc[mt][nt][hf*2], v1 = acc[mt][nt][hf*2+1];
                ssq += v0 * v0 + v1 * v1;
            }
            ssq += __shfl_xor_sync(0xffffffffu, ssq, 1);
            ssq += __shfl_xor_sync(0xffffffffu, ssq, 2);
            if ((lane & 3) == 0) red[rowIdx * 4 + ngrp] = ssq;
        }
    }
    __syncthreads();

    // pass 2: combine partner n-group, normalize, split, store
    #pragma unroll
    for (int mt = 0; mt < 4; mt++) {
        #pragma unroll
        for (int hf = 0; hf < 2; hf++) {
            const int rowIdx = wm + mt * 16 + er + hf * 8;
            const int grow = bm + rowIdx;
            const int bt = grow >> 8;
            const int s  = grow & 255;
            float v[8];
            #pragma unroll
            for (int nt = 0; nt < 4; nt++) {
                v[2*nt]   = acc[mt][nt][hf*2];
                v[2*nt+1] = acc[mt][nt][hf*2+1];
            }
            __nv_bfloat16 *dh, *dl;
            size_t dbase;
            if (gn < DIM) {                    // Q
                float ssq = red[rowIdx * 4 + ngrp] + red[rowIdx * 4 + (ngrp ^ 1)];
                float r = rsqrtf(ssq * (1.0f / HD) + EPSV) * (SCALEV * 2.0f / CAPV);
                #pragma unroll
                for (int j = 0; j < 8; j++) v[j] *= r * wqk[j];
                int h = gn >> 6;
                dh = g_qth; dl = g_qtl;
                dbase = ((size_t)(bt * NH + h) * SEQ + s) * HD;
            } else if (gn < DIM + 256) {       // K
                float ssq = red[rowIdx * 4 + ngrp] + red[rowIdx * 4 + (ngrp ^ 1)];
                float r = rsqrtf(ssq * (1.0f / HD) + EPSV);
                #pragma unroll
                for (int j = 0; j < 8; j++) v[j] *= r;
                int kvh = (gn - DIM) >> 6;
                dh = g_kh; dl = g_kl;
                dbase = ((size_t)(bt * NKV + kvh) * SEQ + s) * HD;
            } else {                            // V
                int kvh = (gn - DIM - 256) >> 6;
                dh = g_vh; dl = g_vl;
                dbase = ((size_t)(bt * NKV + kvh) * SEQ + s) * HD;
            }
            #pragma unroll
            for (int nt = 0; nt < 4; nt++) {
                uint32_t H, L;
                split2(v[2*nt], v[2*nt+1], H, L);
                int col = (wn & 32) + nt * 8 + ec;
                *(uint32_t*)(dh + dbase + col) = H;
                *(uint32_t*)(dl + dbase + col) = L;
            }
        }
    }
}

// ---------------------------------------------------------------------------
// Tensor-core attention: block per (bt, h), 256 threads (8 warps). bf16x3.
// ---------------------------------------------------------------------------
#define ATT_SMEM (6 * 32768 + 1024)

__global__ void __launch_bounds__(256, 1)
attn_mma()
{
    extern __shared__ char smem_raw[];
    uint32_t sbr = smem_u32(smem_raw);
    const uint32_t sb = (sbr + 1023) & ~1023u;
    const uint32_t sQh = sb, sQl = sb + 32768, sKh = sb + 65536,
                   sKl = sb + 98304, sVh = sb + 131072, sVl = sb + 163840;

    const int h  = blockIdx.x;
    const int bt = blockIdx.y;
    const int kvh = h >> 2;
    const int tid = threadIdx.x;
    const int lane = tid & 31;
    const int wid = tid >> 5;

    {
        const size_t qoff = (size_t)(bt * NH + h) * SEQ * HD;
        const size_t koff = (size_t)(bt * NKV + kvh) * SEQ * HD;
        const __nv_bfloat16* srcs[6] = {
            g_qth + qoff, g_qtl + qoff, g_kh + koff, g_kl + koff,
            g_vh + koff, g_vl + koff };
        #pragma unroll
        for (int t = 0; t < 6; t++) {
            const __nv_bfloat16* s = srcs[t];
            const uint32_t dtile = sb + t * 32768;
            #pragma unroll
            for (int i = 0; i < 8; i++) {
                uint32_t q = tid + i * 256;
                uint32_t row = q >> 3, j = q & 7;
                cp16(dtile + ASW(row * 128 + j * 16), s + row * 64 + j * 8);
            }
        }
        asm volatile("cp.async.commit_group;" ::: "memory");
        asm volatile("cp.async.wait_group 0;" ::: "memory");
    }
    __syncthreads();

    const int qm = wid * 32;
    float acc[2][8][4];
    float rsum[2][2];
    #pragma unroll
    for (int i = 0; i < 2; i++) {
        rsum[i][0] = rsum[i][1] = 0.f;
        #pragma unroll
        for (int j = 0; j < 8; j++)
            #pragma unroll
            for (int e = 0; e < 4; e++) acc[i][j][e] = 0.f;
    }

    for (int kb = 0; kb < 4; kb++) {
        float S[2][8][4];
        #pragma unroll
        for (int i = 0; i < 2; i++)
            #pragma unroll
            for (int j = 0; j < 8; j++)
                #pragma unroll
                for (int e = 0; e < 4; e++) S[i][j][e] = 0.f;

        #pragma unroll
        for (int ks = 0; ks < 4; ks++) {
            uint32_t fQh[2][4], fQl[2][4];
            #pragma unroll
            for (int mt = 0; mt < 2; mt++) {
                uint32_t off = ASW((uint32_t)((qm + mt*16 + (lane & 15)) * 128
                              + ks * 32 + ((lane >> 4) & 1) * 16));
                ldmx4(fQh[mt], sQh + off);
                ldmx4(fQl[mt], sQl + off);
            }
            uint32_t fKh[8][2], fKl[8][2];
            #pragma unroll
            for (int np = 0; np < 4; np++) {
                uint32_t krow = kb*64 + np*16 + (lane & 7) + ((lane >> 4) & 1) * 8;
                uint32_t off = ASW(krow * 128 + ks * 32 + ((lane >> 3) & 1) * 16);
                uint32_t t[4];
                ldmx4(t, sKh + off);
                fKh[2*np][0] = t[0]; fKh[2*np][1] = t[1];
                fKh[2*np+1][0] = t[2]; fKh[2*np+1][1] = t[3];
                ldmx4(t, sKl + off);
                fKl[2*np][0] = t[0]; fKl[2*np][1] = t[1];
                fKl[2*np+1][0] = t[2]; fKl[2*np+1][1] = t[3];
            }
            #pragma unroll
            for (int mt = 0; mt < 2; mt++)
                #pragma unroll
                for (int nt = 0; nt < 8; nt++) {
                    mma_bf(S[mt][nt], fQh[mt], fKh[nt]);
                    mma_bf(S[mt][nt], fQh[mt], fKl[nt]);
                    mma_bf(S[mt][nt], fQl[mt], fKh[nt]);
                }
        }

        uint32_t pAh[2][4][4], pAl[2][4][4];
        #pragma unroll
        for (int mt = 0; mt < 2; mt++) {
            #pragma unroll
            for (int nt = 0; nt < 8; nt++) {
                #pragma unroll
                for (int e = 0; e < 4; e++) {
                    float uu = __expf(S[mt][nt][e]);
                    S[mt][nt][e] = __expf(__fdividef(-2.0f * CAPV, uu + 1.0f));
                }
                rsum[mt][0] += S[mt][nt][0] + S[mt][nt][1];
                rsum[mt][1] += S[mt][nt][2] + S[mt][nt][3];
            }
            #pragma unroll
            for (int kk = 0; kk < 4; kk++) {
                split2(S[mt][2*kk][0],   S[mt][2*kk][1],   pAh[mt][kk][0], pAl[mt][kk][0]);
                split2(S[mt][2*kk][2],   S[mt][2*kk][3],   pAh[mt][kk][1], pAl[mt][kk][1]);
                split2(S[mt][2*kk+1][0], S[mt][2*kk+1][1], pAh[mt][kk][2], pAl[mt][kk][2]);
                split2(S[mt][2*kk+1][2], S[mt][2*kk+1][3], pAh[mt][kk][3], pAl[mt][kk][3]);
            }
        }

        #pragma unroll
        for (int kk = 0; kk < 4; kk++) {
            uint32_t fVh[8][2], fVl[8][2];
            #pragma unroll
            for (int np = 0; np < 4; np++) {
                uint32_t vrow = kb*64 + kk*16 + (lane & 7) + ((lane >> 3) & 1) * 8;
                uint32_t off = ASW(vrow * 128 + (np*16 + ((lane >> 4) & 1) * 8) * 2);
                uint32_t t[4];
                ldmx4t(t, sVh + off);
                fVh[2*np][0] = t[0]; fVh[2*np][1] = t[1];
                fVh[2*np+1][0] = t[2]; fVh[2*np+1][1] = t[3];
                ldmx4t(t, sVl + off);
                fVl[2*np][0] = t[0]; fVl[2*np][1] = t[1];
                fVl[2*np+1][0] = t[2]; fVl[2*np+1][1] = t[3];
            }
            #pragma unroll
            for (int mt = 0; mt < 2; mt++)
                #pragma unroll
                for (int nt = 0; nt < 8; nt++) {
                    mma_bf(acc[mt][nt], pAh[mt][kk], fVh[nt]);
                    mma_bf(acc[mt][nt], pAh[mt][kk], fVl[nt]);
                    mma_bf(acc[mt][nt], pAl[mt][kk], fVh[nt]);
                }
        }
    }

    #pragma unroll
    for (int mt = 0; mt < 2; mt++) {
        rsum[mt][0] += __shfl_xor_sync(0xffffffffu, rsum[mt][0], 1);
        rsum[mt][0] += __shfl_xor_sync(0xffffffffu, rsum[mt][0], 2);
        rsum[mt][1] += __shfl_xor_sync(0xffffffffu, rsum[mt][1], 1);
        rsum[mt][1] += __shfl_xor_sync(0xffffffffu, rsum[mt][1], 2);
    }
    #pragma unroll
    for (int mt = 0; mt < 2; mt++) {
        const float inv0 = 1.0f / rsum[mt][0];
        const float inv1 = 1.0f / rsum[mt][1];
        #pragma unroll
        for (int nt = 0; nt < 8; nt++) {
            int rq_ = qm + mt*16 + (lane >> 2);
            int col = nt*8 + (lane & 3) * 2;
            size_t o0 = (size_t)(bt * SEQ + rq_) * GK + h * HD + col;
            size_t o1 = o0 + (size_t)8 * GK;
            *(__half2*)(g_a16 + o0) =
                __floats2half2_rn(acc[mt][nt][0] * inv0, acc[mt][nt][1] * inv0);
            *(__half2*)(g_a16 + o1) =
                __floats2half2_rn(acc[mt][nt][2] * inv1, acc[mt][nt][3] * inv1);
        }
    }
}

// ---------------------------------------------------------------------------
// launch
// ---------------------------------------------------------------------------
extern "C" void kernel_launch(void* const* d_in, const int* in_sizes, int n_in,
                              void* d_out, int out_size)
{
    const float* x  = (const float*)d_in[0];
    const float* Wq = (const float*)d_in[1];
    const float* Wk = (const float*)d_in[2];
    const float* Wv = (const float*)d_in[3];
    const float* Wo = (const float*)d_in[4];
    const float* qw = (const float*)d_in[5];
    const float* kw = (const float*)d_in[6];
    float* out = (float*)d_out;

    static __half *x16 = nullptr, *a16, *w1h, *w1l, *w2h, *w2l;
    if (!x16) {
        cudaGetSymbolAddress((void**)&x16, g_x16);
        cudaGetSymbolAddress((void**)&a16, g_a16);
        cudaGetSymbolAddress((void**)&w1h, g_w1h);
        cudaGetSymbolAddress((void**)&w1l, g_w1l);
        cudaGetSymbolAddress((void**)&w2h, g_w2h);
        cudaGetSymbolAddress((void**)&w2l, g_w2l);
        cudaFuncSetAttribute(attn_mma,
                             cudaFuncAttributeMaxDynamicSharedMemorySize, ATT_SMEM);
        cudaFuncSetAttribute(gemm_mma<0>,
                             cudaFuncAttributeMaxDynamicSharedMemorySize, SMEM_GEMM);
        cudaFuncSetAttribute(gemm_mma<1>,
                             cudaFuncAttributeMaxDynamicSharedMemorySize, SMEM_GEMM);
    }

    const int n4 = MROWS * GK / 4;
    cvt_half<<<(n4 + 255) / 256, 256>>>(x, x16, n4);
    xpose_qkv<<<(QKVC * GK + 255) / 256, 256>>>(Wq, Wk, Wv, w1h, w1l);
    xpose_wo<<<(DIM * GK + 255) / 256, 256>>>(Wo, w2h, w2l);

    gemm_mma<1><<<dim3(QKVC / 128, MROWS / 128), 256, SMEM_GEMM>>>(
        x16, w1h, w1l, nullptr, 0, qw, kw);

    attn_mma<<<dim3(NH, BTN), 256, ATT_SMEM>>>();

    gemm_mma<0><<<dim3(DIM / 128, MROWS / 128), 256, SMEM_GEMM>>>(
        a16, w2h, w2l, out, DIM, nullptr, nullptr);
}

// round 12
// speedup vs baseline: 1.0383x; 1.0383x over previous
#include <cuda_runtime.h>
#include <cuda_bf16.h>
#include <cuda_fp16.h>
#include <math.h>
#include <stdint.h>

// Problem constants
#define BTN   128
#define SEQ   256
#define DIM   1024
#define NH    16
#define NKV   4
#define GRP   4
#define HD    64
#define MROWS (BTN*SEQ)      // 32768
#define QKVC  1536
#define GK    1024
#define EPSV  1e-6f
#define SCALEV 0.125f
#define CAPV  50.0f

// ---------------------------------------------------------------------------
// Scratch (device globals)
// ---------------------------------------------------------------------------
__device__ __align__(16) __half g_x16[(size_t)MROWS * GK];        // x as fp16
__device__ __align__(16) __half g_a16[(size_t)MROWS * GK];        // attn out fp16
__device__ __align__(16) __half g_w1h[(size_t)QKVC * GK];         // [n][k] hi
__device__ __align__(16) __half g_w1l[(size_t)QKVC * GK];         // [n][k] lo
__device__ __align__(16) __half g_w2h[(size_t)DIM * GK];
__device__ __align__(16) __half g_w2l[(size_t)DIM * GK];
// attention tiles (bf16 hi/lo)
__device__ __align__(16) __nv_bfloat16 g_qth[(size_t)MROWS * GK];
__device__ __align__(16) __nv_bfloat16 g_qtl[(size_t)MROWS * GK];
__device__ __align__(16) __nv_bfloat16 g_kh[(size_t)MROWS * 256];
__device__ __align__(16) __nv_bfloat16 g_kl[(size_t)MROWS * 256];
__device__ __align__(16) __nv_bfloat16 g_vh[(size_t)MROWS * 256];
__device__ __align__(16) __nv_bfloat16 g_vl[(size_t)MROWS * 256];

// ---------------------------------------------------------------------------
// helpers
// ---------------------------------------------------------------------------
__device__ __forceinline__ uint32_t smem_u32(const void* p) {
    uint32_t a;
    asm("{ .reg .u64 t; cvta.to.shared.u64 t, %1; cvt.u32.u64 %0, t; }"
        : "=r"(a) : "l"(p));
    return a;
}
__device__ __forceinline__ void cp16(uint32_t dst, const void* src) {
    asm volatile("cp.async.cg.shared.global [%0], [%1], 16;" :: "r"(dst), "l"(src));
}
__device__ __forceinline__ void ldmx4(uint32_t r[4], uint32_t addr) {
    asm volatile("ldmatrix.sync.aligned.m8n8.x4.shared.b16 {%0,%1,%2,%3}, [%4];"
                 : "=r"(r[0]), "=r"(r[1]), "=r"(r[2]), "=r"(r[3]) : "r"(addr));
}
__device__ __forceinline__ void ldmx4t(uint32_t r[4], uint32_t addr) {
    asm volatile("ldmatrix.sync.aligned.m8n8.x4.trans.shared.b16 {%0,%1,%2,%3}, [%4];"
                 : "=r"(r[0]), "=r"(r[1]), "=r"(r[2]), "=r"(r[3]) : "r"(addr));
}
__device__ __forceinline__ void mma_bf(float c[4], const uint32_t a[4],
                                       const uint32_t b[2]) {
    asm volatile("mma.sync.aligned.m16n8k16.row.col.f32.bf16.bf16.f32 "
                 "{%0,%1,%2,%3}, {%4,%5,%6,%7}, {%8,%9}, {%0,%1,%2,%3};"
                 : "+f"(c[0]), "+f"(c[1]), "+f"(c[2]), "+f"(c[3])
                 : "r"(a[0]), "r"(a[1]), "r"(a[2]), "r"(a[3]),
                   "r"(b[0]), "r"(b[1]));
}
__device__ __forceinline__ void mma_fp(float c[4], const uint32_t a[4],
                                       const uint32_t b[2]) {
    asm volatile("mma.sync.aligned.m16n8k16.row.col.f32.f16.f16.f32 "
                 "{%0,%1,%2,%3}, {%4,%5,%6,%7}, {%8,%9}, {%0,%1,%2,%3};"
                 : "+f"(c[0]), "+f"(c[1]), "+f"(c[2]), "+f"(c[3])
                 : "r"(a[0]), "r"(a[1]), "r"(a[2]), "r"(a[3]),
                   "r"(b[0]), "r"(b[1]));
}
__device__ __forceinline__ void split2(float a, float b, uint32_t& H, uint32_t& L) {
    __nv_bfloat16 ah = __float2bfloat16(a), bh = __float2bfloat16(b);
    __nv_bfloat162 hh(ah, bh);
    H = *(uint32_t*)&hh;
    __nv_bfloat162 ll(__float2bfloat16(a - __bfloat162float(ah)),
                      __float2bfloat16(b - __bfloat162float(bh)));
    L = *(uint32_t*)&ll;
}
// soft-capped softmax numerator: input x = z/CAP (|x| <= 0.16 by Cauchy-Schwarz),
// p = exp(CAP*tanh(x) - CAP) via odd Taylor of tanh + single ex2.approx.
__device__ __forceinline__ float softcap_p(float x) {
    float x2 = x * x;
    float t  = fmaf(x2, fmaf(x2, fmaf(x2, -0.05396825f, 0.13333334f),
                             -0.33333334f), 1.0f);
    float arg = fmaf(x * t, 72.134752f, -72.134752f);   // CAP*log2e*(tanh-1)
    float p;
    asm("ex2.approx.ftz.f32 %0, %1;" : "=f"(p) : "f"(arg));
    return p;
}
#define ASW(o) ((o) ^ (((o) >> 3) & 0x70))

// ---------------------------------------------------------------------------
// conversions
// ---------------------------------------------------------------------------
__global__ void cvt_half(const float* __restrict__ in,
                         __half* __restrict__ out, int n4)
{
    int i = blockIdx.x * blockDim.x + threadIdx.x;
    if (i >= n4) return;
    float4 v = ((const float4*)in)[i];
    __half2* op = (__half2*)out;
    op[2*i]   = __floats2half2_rn(v.x, v.y);
    op[2*i+1] = __floats2half2_rn(v.z, v.w);
}

__global__ void xpose_qkv(const float* __restrict__ Wq, const float* __restrict__ Wk,
                          const float* __restrict__ Wv,
                          __half* __restrict__ th, __half* __restrict__ tl)
{
    size_t idx = (size_t)blockIdx.x * blockDim.x + threadIdx.x;
    if (idx >= (size_t)QKVC * GK) return;
    int k = (int)(idx & (GK - 1));
    int n = (int)(idx >> 10);
    float v;
    if (n < DIM)            v = Wq[(size_t)k * (NH*HD)  + n];
    else if (n < DIM + 256) v = Wk[(size_t)k * (NKV*HD) + (n - DIM)];
    else                    v = Wv[(size_t)k * (NKV*HD) + (n - DIM - 256)];
    __half hv = __float2half_rn(v);
    th[idx] = hv;
    tl[idx] = __float2half_rn(v - __half2float(hv));
}

__global__ void xpose_wo(const float* __restrict__ W,
                         __half* __restrict__ th, __half* __restrict__ tl)
{
    size_t idx = (size_t)blockIdx.x * blockDim.x + threadIdx.x;
    if (idx >= (size_t)DIM * GK) return;
    int k = (int)(idx & (GK - 1));
    int n = (int)(idx >> 10);
    float v = W[(size_t)k * DIM + n];
    __half hv = __float2half_rn(v);
    th[idx] = hv;
    tl[idx] = __float2half_rn(v - __half2float(hv));
}

// ---------------------------------------------------------------------------
// fp16 2-term GEMM: C[m,n] = A[m,:].(Bh[n,:]+Bl[n,:]),  K=1024
// 128x128 CTA tile, 8 warps (32x64 warp tiles), BK=64, 2-stage, SW128
// swizzled smem (128B rows, no padding), 2 CTAs/SM.   [round-10 config]
// EPI=0: plain fp32 store.  EPI=1: QKV epilogue (rmsnorm fold + bf16 split).
// ---------------------------------------------------------------------------
#define BK      64
#define NCHUNK  (GK / BK)             // 16
#define TILE_B  (128 * 128)           // 16384 (128 rows x 128B)
#define OFF_A   0
#define OFF_BH  TILE_B
#define OFF_BL  (2*TILE_B)
#define STG     (3*TILE_B)            // 49152
#define SMEM_GEMM (2 * STG + 1024)    // 99328

__device__ __forceinline__ void g_load(uint32_t sbase, int tid,
    const __half* A, const __half* Bh, const __half* Bl, int koff)
{
    #pragma unroll
    for (int it = 0; it < 4; it++) {
        int g = tid + it * 256;            // 0..1023 granules per array
        int row = g >> 3;
        int j   = g & 7;
        uint32_t dst = sbase + ASW((uint32_t)(row * 128 + j * 16));
        size_t so = (size_t)row * GK + koff + j * 8;
        cp16(dst + OFF_A,  A  + so);
        cp16(dst + OFF_BH, Bh + so);
        cp16(dst + OFF_BL, Bl + so);
    }
    asm volatile("cp.async.commit_group;" ::: "memory");
}

template<int EPI>
__global__ void __launch_bounds__(256, 2)
gemm_mma(const __half* __restrict__ a, const __half* __restrict__ bh,
         const __half* __restrict__ bl, float* __restrict__ C, int ldc,
         const float* __restrict__ qw, const float* __restrict__ kw)
{
    extern __shared__ char smem_raw[];
    uint32_t sbr = smem_u32(smem_raw);
    const uint32_t sb = (sbr + 1023) & ~1023u;
    const int tid  = threadIdx.x;
    const int wid  = tid >> 5;
    const int lane = tid & 31;
    const int bm = blockIdx.y * 128;
    const int bn = blockIdx.x * 128;

    const __half* A  = a  + (size_t)bm * GK;
    const __half* Bh = bh + (size_t)bn * GK;
    const __half* Bl = bl + (size_t)bn * GK;

    const int wm = (wid & 3) * 32;       // 4 m positions
    const int wn = (wid >> 2) * 64;      // 2 n positions
    const int ar = lane & 15;
    const int ac = (lane >> 4) * 16;
    const int br = (lane & 7) + ((lane >> 4) & 1) * 8;
    const int bc = ((lane >> 3) & 1) * 16;

    float acc[2][8][4];
    #pragma unroll
    for (int i = 0; i < 2; i++)
        #pragma unroll
        for (int j = 0; j < 8; j++)
            #pragma unroll
            for (int e = 0; e < 4; e++) acc[i][j][e] = 0.f;

    g_load(sb, tid, A, Bh, Bl, 0);

    for (int c = 0; c < NCHUNK; c++) {
        asm volatile("cp.async.wait_group 0;" ::: "memory");
        __syncthreads();
        if (c + 1 < NCHUNK)
            g_load(sb + ((c + 1) & 1) * STG, tid, A, Bh, Bl, (c + 1) * BK);

        const uint32_t st = sb + (c & 1) * STG;
        #pragma unroll
        for (int kk = 0; kk < 4; kk++) {
            const int kb = kk * 32;      // byte offset of this k16 within 128B row
            uint32_t fA[2][4];
            #pragma unroll
            for (int mt = 0; mt < 2; mt++) {
                uint32_t off = ASW((uint32_t)((wm + mt * 16 + ar) * 128 + kb + ac));
                ldmx4(fA[mt], st + OFF_A + off);
            }
            uint32_t fBh[8][2], fBl[8][2];
            #pragma unroll
            for (int g = 0; g < 4; g++) {
                uint32_t off = ASW((uint32_t)((wn + g * 16 + br) * 128 + kb + bc));
                uint32_t t[4];
                ldmx4(t, st + OFF_BH + off);
                fBh[2*g][0] = t[0]; fBh[2*g][1] = t[1];
                fBh[2*g+1][0] = t[2]; fBh[2*g+1][1] = t[3];
                ldmx4(t, st + OFF_BL + off);
                fBl[2*g][0] = t[0]; fBl[2*g][1] = t[1];
                fBl[2*g+1][0] = t[2]; fBl[2*g+1][1] = t[3];
            }
            #pragma unroll
            for (int mt = 0; mt < 2; mt++)
                #pragma unroll
                for (int nt = 0; nt < 8; nt++) {
                    mma_fp(acc[mt][nt], fA[mt], fBh[nt]);
                    mma_fp(acc[mt][nt], fA[mt], fBl[nt]);
                }
        }
    }

    const int er = lane >> 2;
    const int ec = (lane & 3) * 2;

    if (EPI == 0) {
        #pragma unroll
        for (int mt = 0; mt < 2; mt++)
            #pragma unroll
            for (int nt = 0; nt < 8; nt++) {
                size_t row0 = (size_t)(bm + wm + mt * 16 + er) * ldc
                            + bn + wn + nt * 8 + ec;
                *(float2*)&C[row0]           = make_float2(acc[mt][nt][0], acc[mt][nt][1]);
                *(float2*)&C[row0 + 8 * ldc] = make_float2(acc[mt][nt][2], acc[mt][nt][3]);
            }
        return;
    }

    // ---- EPI == 1: QKV epilogue with fused rmsnorm + bf16 hi/lo split ----
    const int gn = bn + wn;            // multiple of 64; head-aligned
    float wqk[16];
    if (gn < DIM) {
        #pragma unroll
        for (int nt = 0; nt < 8; nt++) {
            int col = nt * 8 + ec;
            wqk[2*nt]   = __ldg(&qw[col])   * __ldg(&kw[col]);
            wqk[2*nt+1] = __ldg(&qw[col+1]) * __ldg(&kw[col+1]);
        }
    }

    #pragma unroll
    for (int mt = 0; mt < 2; mt++) {
        #pragma unroll
        for (int hf = 0; hf < 2; hf++) {
            const int grow = bm + wm + mt * 16 + er + hf * 8;
            const int bt = grow >> 8;
            const int s  = grow & 255;
            float v[16];
            #pragma unroll
            for (int nt = 0; nt < 8; nt++) {
                v[2*nt]   = acc[mt][nt][hf*2];
                v[2*nt+1] = acc[mt][nt][hf*2+1];
            }
            __nv_bfloat16 *dh, *dl;
            size_t dbase;
            if (gn < DIM) {                    // Q: rmsnorm + qw*kw + scale/CAP
                float ssq = 0.f;
                #pragma unroll
                for (int j = 0; j < 16; j++) ssq += v[j] * v[j];
                ssq += __shfl_xor_sync(0xffffffffu, ssq, 1);
                ssq += __shfl_xor_sync(0xffffffffu, ssq, 2);
                float r = rsqrtf(ssq * (1.0f / HD) + EPSV) * (SCALEV / CAPV);
                #pragma unroll
                for (int j = 0; j < 16; j++) v[j] *= r * wqk[j];
                int h = gn >> 6;
                dh = g_qth; dl = g_qtl;
                dbase = ((size_t)(bt * NH + h) * SEQ + s) * HD;
            } else if (gn < DIM + 256) {       // K: rmsnorm only
                float ssq = 0.f;
                #pragma unroll
                for (int j = 0; j < 16; j++) ssq += v[j] * v[j];
                ssq += __shfl_xor_sync(0xffffffffu, ssq, 1);
                ssq += __shfl_xor_sync(0xffffffffu, ssq, 2);
                float r = rsqrtf(ssq * (1.0f / HD) + EPSV);
                #pragma unroll
                for (int j = 0; j < 16; j++) v[j] *= r;
                int kvh = (gn - DIM) >> 6;
                dh = g_kh; dl = g_kl;
                dbase = ((size_t)(bt * NKV + kvh) * SEQ + s) * HD;
            } else {                            // V: plain
                int kvh = (gn - DIM - 256) >> 6;
                dh = g_vh; dl = g_vl;
                dbase = ((size_t)(bt * NKV + kvh) * SEQ + s) * HD;
            }
            #pragma unroll
            for (int nt = 0; nt < 8; nt++) {
                uint32_t H, L;
                split2(v[2*nt], v[2*nt+1], H, L);
                *(uint32_t*)(dh + dbase + nt * 8 + ec) = H;
                *(uint32_t*)(dl + dbase + nt * 8 + ec) = L;
            }
        }
    }
}

// ---------------------------------------------------------------------------
// Tensor-core attention: block per (bt, h), 256 threads (8 warps). bf16x3.
// Softcap via tanh-Taylor + single ex2 (x = z/CAP from MMA directly).
// ---------------------------------------------------------------------------
#define ATT_SMEM (6 * 32768 + 1024)

__global__ void __launch_bounds__(256, 1)
attn_mma()
{
    extern __shared__ char smem_raw[];
    uint32_t sbr = smem_u32(smem_raw);
    const uint32_t sb = (sbr + 1023) & ~1023u;
    const uint32_t sQh = sb, sQl = sb + 32768, sKh = sb + 65536,
                   sKl = sb + 98304, sVh = sb + 131072, sVl = sb + 163840;

    const int h  = blockIdx.x;
    const int bt = blockIdx.y;
    const int kvh = h >> 2;
    const int tid = threadIdx.x;
    const int lane = tid & 31;
    const int wid = tid >> 5;

    {
        const size_t qoff = (size_t)(bt * NH + h) * SEQ * HD;
        const size_t koff = (size_t)(bt * NKV + kvh) * SEQ * HD;
        const __nv_bfloat16* srcs[6] = {
            g_qth + qoff, g_qtl + qoff, g_kh + koff, g_kl + koff,
            g_vh + koff, g_vl + koff };
        #pragma unroll
        for (int t = 0; t < 6; t++) {
            const __nv_bfloat16* s = srcs[t];
            const uint32_t dtile = sb + t * 32768;
            #pragma unroll
            for (int i = 0; i < 8; i++) {
                uint32_t q = tid + i * 256;
                uint32_t row = q >> 3, j = q & 7;
                cp16(dtile + ASW(row * 128 + j * 16), s + row * 64 + j * 8);
            }
        }
        asm volatile("cp.async.commit_group;" ::: "memory");
        asm volatile("cp.async.wait_group 0;" ::: "memory");
    }
    __syncthreads();

    const int qm = wid * 32;
    float acc[2][8][4];
    float rsum[2][2];
    #pragma unroll
    for (int i = 0; i < 2; i++) {
        rsum[i][0] = rsum[i][1] = 0.f;
        #pragma unroll
        for (int j = 0; j < 8; j++)
            #pragma unroll
            for (int e = 0; e < 4; e++) acc[i][j][e] = 0.f;
    }

    for (int kb = 0; kb < 4; kb++) {
        float S[2][8][4];
        #pragma unroll
        for (int i = 0; i < 2; i++)
            #pragma unroll
            for (int j = 0; j < 8; j++)
                #pragma unroll
                for (int e = 0; e < 4; e++) S[i][j][e] = 0.f;

        #pragma unroll
        for (int ks = 0; ks < 4; ks++) {
            uint32_t fQh[2][4], fQl[2][4];
            #pragma unroll
            for (int mt = 0; mt < 2; mt++) {
                uint32_t off = ASW((uint32_t)((qm + mt*16 + (lane & 15)) * 128
                              + ks * 32 + ((lane >> 4) & 1) * 16));
                ldmx4(fQh[mt], sQh + off);
                ldmx4(fQl[mt], sQl + off);
            }
            uint32_t fKh[8][2], fKl[8][2];
            #pragma unroll
            for (int np = 0; np < 4; np++) {
                uint32_t krow = kb*64 + np*16 + (lane & 7) + ((lane >> 4) & 1) * 8;
                uint32_t off = ASW(krow * 128 + ks * 32 + ((lane >> 3) & 1) * 16);
                uint32_t t[4];
                ldmx4(t, sKh + off);
                fKh[2*np][0] = t[0]; fKh[2*np][1] = t[1];
                fKh[2*np+1][0] = t[2]; fKh[2*np+1][1] = t[3];
                ldmx4(t, sKl + off);
                fKl[2*np][0] = t[0]; fKl[2*np][1] = t[1];
                fKl[2*np+1][0] = t[2]; fKl[2*np+1][1] = t[3];
            }
            #pragma unroll
            for (int mt = 0; mt < 2; mt++)
                #pragma unroll
                for (int nt = 0; nt < 8; nt++) {
                    mma_bf(S[mt][nt], fQh[mt], fKh[nt]);
                    mma_bf(S[mt][nt], fQh[mt], fKl[nt]);
                    mma_bf(S[mt][nt], fQl[mt], fKh[nt]);
                }
        }

        uint32_t pAh[2][4][4], pAl[2][4][4];
        #pragma unroll
        for (int mt = 0; mt < 2; mt++) {
            #pragma unroll
            for (int nt = 0; nt < 8; nt++) {
                #pragma unroll
                for (int e = 0; e < 4; e++)
                    S[mt][nt][e] = softcap_p(S[mt][nt][e]);
                rsum[mt][0] += S[mt][nt][0] + S[mt][nt][1];
                rsum[mt][1] += S[mt][nt][2] + S[mt][nt][3];
            }
            #pragma unroll
            for (int kk = 0; kk < 4; kk++) {
                split2(S[mt][2*kk][0],   S[mt][2*kk][1],   pAh[mt][kk][0], pAl[mt][kk][0]);
                split2(S[mt][2*kk][2],   S[mt][2*kk][3],   pAh[mt][kk][1], pAl[mt][kk][1]);
                split2(S[mt][2*kk+1][0], S[mt][2*kk+1][1], pAh[mt][kk][2], pAl[mt][kk][2]);
                split2(S[mt][2*kk+1][2], S[mt][2*kk+1][3], pAh[mt][kk][3], pAl[mt][kk][3]);
            }
        }

        #pragma unroll
        for (int kk = 0; kk < 4; kk++) {
            uint32_t fVh[8][2], fVl[8][2];
            #pragma unroll
            for (int np = 0; np < 4; np++) {
                uint32_t vrow = kb*64 + kk*16 + (lane & 7) + ((lane >> 3) & 1) * 8;
                uint32_t off = ASW(vrow * 128 + (np*16 + ((lane >> 4) & 1) * 8) * 2);
                uint32_t t[4];
                ldmx4t(t, sVh + off);
                fVh[2*np][0] = t[0]; fVh[2*np][1] = t[1];
                fVh[2*np+1][0] = t[2]; fVh[2*np+1][1] = t[3];
                ldmx4t(t, sVl + off);
                fVl[2*np][0] = t[0]; fVl[2*np][1] = t[1];
                fVl[2*np+1][0] = t[2]; fVl[2*np+1][1] = t[3];
            }
            #pragma unroll
            for (int mt = 0; mt < 2; mt++)
                #pragma unroll
                for (int nt = 0; nt < 8; nt++) {
                    mma_bf(acc[mt][nt], pAh[mt][kk], fVh[nt]);
                    mma_bf(acc[mt][nt], pAh[mt][kk], fVl[nt]);
                    mma_bf(acc[mt][nt], pAl[mt][kk], fVh[nt]);
                }
        }
    }

    #pragma unroll
    for (int mt = 0; mt < 2; mt++) {
        rsum[mt][0] += __shfl_xor_sync(0xffffffffu, rsum[mt][0], 1);
        rsum[mt][0] += __shfl_xor_sync(0xffffffffu, rsum[mt][0], 2);
        rsum[mt][1] += __shfl_xor_sync(0xffffffffu, rsum[mt][1], 1);
        rsum[mt][1] += __shfl_xor_sync(0xffffffffu, rsum[mt][1], 2);
    }
    #pragma unroll
    for (int mt = 0; mt < 2; mt++) {
        const float inv0 = 1.0f / rsum[mt][0];
        const float inv1 = 1.0f / rsum[mt][1];
        #pragma unroll
        for (int nt = 0; nt < 8; nt++) {
            int rq_ = qm + mt*16 + (lane >> 2);
            int col = nt*8 + (lane & 3) * 2;
            size_t o0 = (size_t)(bt * SEQ + rq_) * GK + h * HD + col;
            size_t o1 = o0 + (size_t)8 * GK;
            *(__half2*)(g_a16 + o0) =
                __floats2half2_rn(acc[mt][nt][0] * inv0, acc[mt][nt][1] * inv0);
            *(__half2*)(g_a16 + o1) =
                __floats2half2_rn(acc[mt][nt][2] * inv1, acc[mt][nt][3] * inv1);
        }
    }
}

// ---------------------------------------------------------------------------
// launch
// ---------------------------------------------------------------------------
extern "C" void kernel_launch(void* const* d_in, const int* in_sizes, int n_in,
                              void* d_out, int out_size)
{
    const float* x  = (const float*)d_in[0];
    const float* Wq = (const float*)d_in[1];
    const float* Wk = (const float*)d_in[2];
    const float* Wv = (const float*)d_in[3];
    const float* Wo = (const float*)d_in[4];
    const float* qw = (const float*)d_in[5];
    const float* kw = (const float*)d_in[6];
    float* out = (float*)d_out;

    static __half *x16 = nullptr, *a16, *w1h, *w1l, *w2h, *w2l;
    if (!x16) {
        cudaGetSymbolAddress((void**)&x16, g_x16);
        cudaGetSymbolAddress((void**)&a16, g_a16);
        cudaGetSymbolAddress((void**)&w1h, g_w1h);
        cudaGetSymbolAddress((void**)&w1l, g_w1l);
        cudaGetSymbolAddress((void**)&w2h, g_w2h);
        cudaGetSymbolAddress((void**)&w2l, g_w2l);
        cudaFuncSetAttribute(attn_mma,
                             cudaFuncAttributeMaxDynamicSharedMemorySize, ATT_SMEM);
        cudaFuncSetAttribute(gemm_mma<0>,
                             cudaFuncAttributeMaxDynamicSharedMemorySize, SMEM_GEMM);
        cudaFuncSetAttribute(gemm_mma<1>,
                             cudaFuncAttributeMaxDynamicSharedMemorySize, SMEM_GEMM);
    }

    const int n4 = MROWS * GK / 4;
    cvt_half<<<(n4 + 255) / 256, 256>>>(x, x16, n4);
    xpose_qkv<<<(QKVC * GK + 255) / 256, 256>>>(Wq, Wk, Wv, w1h, w1l);
    xpose_wo<<<(DIM * GK + 255) / 256, 256>>>(Wo, w2h, w2l);

    gemm_mma<1><<<dim3(QKVC / 128, MROWS / 128), 256, SMEM_GEMM>>>(
        x16, w1h, w1l, nullptr, 0, qw, kw);

    attn_mma<<<dim3(NH, BTN), 256, ATT_SMEM>>>();

    gemm_mma<0><<<dim3(DIM / 128, MROWS / 128), 256, SMEM_GEMM>>>(
        a16, w2h, w2l, out, DIM, nullptr, nullptr);
}

// round 14
// speedup vs baseline: 1.1380x; 1.0960x over previous
#include <cuda_runtime.h>
#include <cuda_bf16.h>
#include <cuda_fp16.h>
#include <math.h>
#include <stdint.h>

// Problem constants
#define BTN   128
#define SEQ   256
#define DIM   1024
#define NH    16
#define NKV   4
#define GRP   4
#define HD    64
#define MROWS (BTN*SEQ)      // 32768
#define QKVC  1536
#define GK    1024
#define EPSV  1e-6f
#define SCALEV 0.125f
#define CAPV  50.0f

// ---------------------------------------------------------------------------
// Scratch (device globals)
// ---------------------------------------------------------------------------
__device__ __align__(16) __half g_x16[(size_t)MROWS * GK];        // x as fp16
__device__ __align__(16) __half g_a16[(size_t)MROWS * GK];        // attn out fp16
__device__ __align__(16) __half g_w1h[(size_t)QKVC * GK];         // [n][k] hi
__device__ __align__(16) __half g_w1l[(size_t)QKVC * GK];         // [n][k] lo
__device__ __align__(16) __half g_w2h[(size_t)DIM * GK];
__device__ __align__(16) __half g_w2l[(size_t)DIM * GK];
// attention tiles (fp16)
__device__ __align__(16) __half g_qt16[(size_t)MROWS * GK];       // Q tiles (single)
__device__ __align__(16) __half g_k16h[(size_t)MROWS * 256];      // K hi
__device__ __align__(16) __half g_k16l[(size_t)MROWS * 256];      // K lo
__device__ __align__(16) __half g_v16h[(size_t)MROWS * 256];      // V hi
__device__ __align__(16) __half g_v16l[(size_t)MROWS * 256];      // V lo

// ---------------------------------------------------------------------------
// helpers
// ---------------------------------------------------------------------------
__device__ __forceinline__ uint32_t smem_u32(const void* p) {
    uint32_t a;
    asm("{ .reg .u64 t; cvta.to.shared.u64 t, %1; cvt.u32.u64 %0, t; }"
        : "=r"(a) : "l"(p));
    return a;
}
__device__ __forceinline__ void cp16(uint32_t dst, const void* src) {
    asm volatile("cp.async.cg.shared.global [%0], [%1], 16;" :: "r"(dst), "l"(src));
}
__device__ __forceinline__ void ldmx4(uint32_t r[4], uint32_t addr) {
    asm volatile("ldmatrix.sync.aligned.m8n8.x4.shared.b16 {%0,%1,%2,%3}, [%4];"
                 : "=r"(r[0]), "=r"(r[1]), "=r"(r[2]), "=r"(r[3]) : "r"(addr));
}
__device__ __forceinline__ void ldmx4t(uint32_t r[4], uint32_t addr) {
    asm volatile("ldmatrix.sync.aligned.m8n8.x4.trans.shared.b16 {%0,%1,%2,%3}, [%4];"
                 : "=r"(r[0]), "=r"(r[1]), "=r"(r[2]), "=r"(r[3]) : "r"(addr));
}
__device__ __forceinline__ void mma_fp(float c[4], const uint32_t a[4],
                                       const uint32_t b[2]) {
    asm volatile("mma.sync.aligned.m16n8k16.row.col.f32.f16.f16.f32 "
                 "{%0,%1,%2,%3}, {%4,%5,%6,%7}, {%8,%9}, {%0,%1,%2,%3};"
                 : "+f"(c[0]), "+f"(c[1]), "+f"(c[2]), "+f"(c[3])
                 : "r"(a[0]), "r"(a[1]), "r"(a[2]), "r"(a[3]),
                   "r"(b[0]), "r"(b[1]));
}
__device__ __forceinline__ void split2h(float a, float b, uint32_t& H, uint32_t& L) {
    __half ah = __float2half_rn(a), bh = __float2half_rn(b);
    __half2 hh(ah, bh);
    H = *(uint32_t*)&hh;
    __half2 ll(__float2half_rn(a - __half2float(ah)),
               __float2half_rn(b - __half2float(bh)));
    L = *(uint32_t*)&ll;
}
// soft-capped softmax numerator, UNSHIFTED (constant cancels in normalization).
// Input y = z*SCALE (|y| <= 8 by Cauchy-Schwarz after rmsnorm).
// p = exp(CAP*tanh(y/CAP)) in [e^-8, e^8] -- fp16-representable.
// tanh via odd Taylor with 1/CAP^2 powers folded into coefficients.
__device__ __forceinline__ float softcap_p(float y) {
    float u = y * y;
    float t = fmaf(u, fmaf(u, fmaf(u, -3.4540e-12f, 2.1333334e-8f),
                            -1.3333334e-4f), 1.0f);
    float arg = (y * t) * 1.44269504f;
    float p;
    asm("ex2.approx.ftz.f32 %0, %1;" : "=f"(p) : "f"(arg));
    return p;
}
#define ASW(o) ((o) ^ (((o) >> 3) & 0x70))

// ---------------------------------------------------------------------------
// conversions
// ---------------------------------------------------------------------------
__global__ void cvt_half(const float* __restrict__ in,
                         __half* __restrict__ out, int n4)
{
    int i = blockIdx.x * blockDim.x + threadIdx.x;
    if (i >= n4) return;
    float4 v = ((const float4*)in)[i];
    __half2* op = (__half2*)out;
    op[2*i]   = __floats2half2_rn(v.x, v.y);
    op[2*i+1] = __floats2half2_rn(v.z, v.w);
}

__global__ void xpose_qkv(const float* __restrict__ Wq, const float* __restrict__ Wk,
                          const float* __restrict__ Wv,
                          __half* __restrict__ th, __half* __restrict__ tl)
{
    size_t idx = (size_t)blockIdx.x * blockDim.x + threadIdx.x;
    if (idx >= (size_t)QKVC * GK) return;
    int k = (int)(idx & (GK - 1));
    int n = (int)(idx >> 10);
    float v;
    if (n < DIM)            v = Wq[(size_t)k * (NH*HD)  + n];
    else if (n < DIM + 256) v = Wk[(size_t)k * (NKV*HD) + (n - DIM)];
    else                    v = Wv[(size_t)k * (NKV*HD) + (n - DIM - 256)];
    __half hv = __float2half_rn(v);
    th[idx] = hv;
    tl[idx] = __float2half_rn(v - __half2float(hv));
}

__global__ void xpose_wo(const float* __restrict__ W,
                         __half* __restrict__ th, __half* __restrict__ tl)
{
    size_t idx = (size_t)blockIdx.x * blockDim.x + threadIdx.x;
    if (idx >= (size_t)DIM * GK) return;
    int k = (int)(idx & (GK - 1));
    int n = (int)(idx >> 10);
    float v = W[(size_t)k * DIM + n];
    __half hv = __float2half_rn(v);
    th[idx] = hv;
    tl[idx] = __float2half_rn(v - __half2float(hv));
}

// ---------------------------------------------------------------------------
// fp16 2-term GEMM: C[m,n] = A[m,:].(Bh[n,:]+Bl[n,:]),  K=1024
// 128x128 CTA tile, 8 warps (32x64 warp tiles), BK=64, 2-stage, SW128
// swizzled smem, 2 CTAs/SM.   [round-10 config]
// EPI=0: plain fp32 store.  EPI=1: QKV epilogue (rmsnorm fold + fp16 split).
// ---------------------------------------------------------------------------
#define BK      64
#define NCHUNK  (GK / BK)             // 16
#define TILE_B  (128 * 128)           // 16384 (128 rows x 128B)
#define OFF_A   0
#define OFF_BH  TILE_B
#define OFF_BL  (2*TILE_B)
#define STG     (3*TILE_B)            // 49152
#define SMEM_GEMM (2 * STG + 1024)    // 99328

__device__ __forceinline__ void g_load(uint32_t sbase, int tid,
    const __half* A, const __half* Bh, const __half* Bl, int koff)
{
    #pragma unroll
    for (int it = 0; it < 4; it++) {
        int g = tid + it * 256;            // 0..1023 granules per array
        int row = g >> 3;
        int j   = g & 7;
        uint32_t dst = sbase + ASW((uint32_t)(row * 128 + j * 16));
        size_t so = (size_t)row * GK + koff + j * 8;
        cp16(dst + OFF_A,  A  + so);
        cp16(dst + OFF_BH, Bh + so);
        cp16(dst + OFF_BL, Bl + so);
    }
    asm volatile("cp.async.commit_group;" ::: "memory");
}

template<int EPI>
__global__ void __launch_bounds__(256, 2)
gemm_mma(const __half* __restrict__ a, const __half* __restrict__ bh,
         const __half* __restrict__ bl, float* __restrict__ C, int ldc,
         const float* __restrict__ qw, const float* __restrict__ kw)
{
    extern __shared__ char smem_raw[];
    uint32_t sbr = smem_u32(smem_raw);
    const uint32_t sb = (sbr + 1023) & ~1023u;
    const int tid  = threadIdx.x;
    const int wid  = tid >> 5;
    const int lane = tid & 31;
    const int bm = blockIdx.y * 128;
    const int bn = blockIdx.x * 128;

    const __half* A  = a  + (size_t)bm * GK;
    const __half* Bh = bh + (size_t)bn * GK;
    const __half* Bl = bl + (size_t)bn * GK;

    const int wm = (wid & 3) * 32;       // 4 m positions
    const int wn = (wid >> 2) * 64;      // 2 n positions
    const int ar = lane & 15;
    const int ac = (lane >> 4) * 16;
    const int br = (lane & 7) + ((lane >> 4) & 1) * 8;
    const int bc = ((lane >> 3) & 1) * 16;

    float acc[2][8][4];
    #pragma unroll
    for (int i = 0; i < 2; i++)
        #pragma unroll
        for (int j = 0; j < 8; j++)
            #pragma unroll
            for (int e = 0; e < 4; e++) acc[i][j][e] = 0.f;

    g_load(sb, tid, A, Bh, Bl, 0);

    for (int c = 0; c < NCHUNK; c++) {
        asm volatile("cp.async.wait_group 0;" ::: "memory");
        __syncthreads();
        if (c + 1 < NCHUNK)
            g_load(sb + ((c + 1) & 1) * STG, tid, A, Bh, Bl, (c + 1) * BK);

        const uint32_t st = sb + (c & 1) * STG;
        #pragma unroll
        for (int kk = 0; kk < 4; kk++) {
            const int kb = kk * 32;
            uint32_t fA[2][4];
            #pragma unroll
            for (int mt = 0; mt < 2; mt++) {
                uint32_t off = ASW((uint32_t)((wm + mt * 16 + ar) * 128 + kb + ac));
                ldmx4(fA[mt], st + OFF_A + off);
            }
            uint32_t fBh[8][2], fBl[8][2];
            #pragma unroll
            for (int g = 0; g < 4; g++) {
                uint32_t off = ASW((uint32_t)((wn + g * 16 + br) * 128 + kb + bc));
                uint32_t t[4];
                ldmx4(t, st + OFF_BH + off);
                fBh[2*g][0] = t[0]; fBh[2*g][1] = t[1];
                fBh[2*g+1][0] = t[2]; fBh[2*g+1][1] = t[3];
                ldmx4(t, st + OFF_BL + off);
                fBl[2*g][0] = t[0]; fBl[2*g][1] = t[1];
                fBl[2*g+1][0] = t[2]; fBl[2*g+1][1] = t[3];
            }
            #pragma unroll
            for (int mt = 0; mt < 2; mt++)
                #pragma unroll
                for (int nt = 0; nt < 8; nt++) {
                    mma_fp(acc[mt][nt], fA[mt], fBh[nt]);
                    mma_fp(acc[mt][nt], fA[mt], fBl[nt]);
                }
        }
    }

    const int er = lane >> 2;
    const int ec = (lane & 3) * 2;

    if (EPI == 0) {
        #pragma unroll
        for (int mt = 0; mt < 2; mt++)
            #pragma unroll
            for (int nt = 0; nt < 8; nt++) {
                size_t row0 = (size_t)(bm + wm + mt * 16 + er) * ldc
                            + bn + wn + nt * 8 + ec;
                *(float2*)&C[row0]           = make_float2(acc[mt][nt][0], acc[mt][nt][1]);
                *(float2*)&C[row0 + 8 * ldc] = make_float2(acc[mt][nt][2], acc[mt][nt][3]);
            }
        return;
    }

    // ---- EPI == 1: QKV epilogue, rmsnorm fold + fp16 tile writes ----
    const int gn = bn + wn;            // multiple of 64; head-aligned
    float wqk[16];
    if (gn < DIM) {
        #pragma unroll
        for (int nt = 0; nt < 8; nt++) {
            int col = nt * 8 + ec;
            wqk[2*nt]   = __ldg(&qw[col])   * __ldg(&kw[col]);
            wqk[2*nt+1] = __ldg(&qw[col+1]) * __ldg(&kw[col+1]);
        }
    }

    #pragma unroll
    for (int mt = 0; mt < 2; mt++) {
        #pragma unroll
        for (int hf = 0; hf < 2; hf++) {
            const int grow = bm + wm + mt * 16 + er + hf * 8;
            const int bt = grow >> 8;
            const int s  = grow & 255;
            float v[16];
            #pragma unroll
            for (int nt = 0; nt < 8; nt++) {
                v[2*nt]   = acc[mt][nt][hf*2];
                v[2*nt+1] = acc[mt][nt][hf*2+1];
            }
            if (gn < DIM) {                    // Q: rmsnorm + qw*kw + SCALE
                float ssq = 0.f;
                #pragma unroll
                for (int j = 0; j < 16; j++) ssq += v[j] * v[j];
                ssq += __shfl_xor_sync(0xffffffffu, ssq, 1);
                ssq += __shfl_xor_sync(0xffffffffu, ssq, 2);
                float r = rsqrtf(ssq * (1.0f / HD) + EPSV) * SCALEV;
                int h = gn >> 6;
                size_t dbase = ((size_t)(bt * NH + h) * SEQ + s) * HD;
                #pragma unroll
                for (int nt = 0; nt < 8; nt++) {
                    __half2 hp = __floats2half2_rn(v[2*nt] * r * wqk[2*nt],
                                                   v[2*nt+1] * r * wqk[2*nt+1]);
                    *(__half2*)(g_qt16 + dbase + nt * 8 + ec) = hp;
                }
            } else if (gn < DIM + 256) {       // K: rmsnorm, fp16 hi/lo
                float ssq = 0.f;
                #pragma unroll
                for (int j = 0; j < 16; j++) ssq += v[j] * v[j];
                ssq += __shfl_xor_sync(0xffffffffu, ssq, 1);
                ssq += __shfl_xor_sync(0xffffffffu, ssq, 2);
                float r = rsqrtf(ssq * (1.0f / HD) + EPSV);
                int kvh = (gn - DIM) >> 6;
                size_t dbase = ((size_t)(bt * NKV + kvh) * SEQ + s) * HD;
                #pragma unroll
                for (int nt = 0; nt < 8; nt++) {
                    uint32_t H, L;
                    split2h(v[2*nt] * r, v[2*nt+1] * r, H, L);
                    *(uint32_t*)(g_k16h + dbase + nt * 8 + ec) = H;
                    *(uint32_t*)(g_k16l + dbase + nt * 8 + ec) = L;
                }
            } else {                            // V: plain fp16 hi/lo
                int kvh = (gn - DIM - 256) >> 6;
                size_t dbase = ((size_t)(bt * NKV + kvh) * SEQ + s) * HD;
                #pragma unroll
                for (int nt = 0; nt < 8; nt++) {
                    uint32_t H, L;
                    split2h(v[2*nt], v[2*nt+1], H, L);
                    *(uint32_t*)(g_v16h + dbase + nt * 8 + ec) = H;
                    *(uint32_t*)(g_v16l + dbase + nt * 8 + ec) = L;
                }
            }
        }
    }
}

// ---------------------------------------------------------------------------
// Tensor-core attention: block per (bt, h), 256 threads (8 warps).
// Q single fp16, K fp16 hi/lo, P single fp16 (UNSHIFTED softcap numerator),
// V fp16 hi/lo.
// ---------------------------------------------------------------------------
#define ATT_SMEM (5 * 32768 + 1024)

__global__ void __launch_bounds__(256, 1)
attn_mma()
{
    extern __shared__ char smem_raw[];
    uint32_t sbr = smem_u32(smem_raw);
    const uint32_t sb = (sbr + 1023) & ~1023u;
    const uint32_t sQ = sb, sKh = sb + 32768, sKl = sb + 65536,
                   sVh = sb + 98304, sVl = sb + 131072;

    const int h  = blockIdx.x;
    const int bt = blockIdx.y;
    const int kvh = h >> 2;
    const int tid = threadIdx.x;
    const int lane = tid & 31;
    const int wid = tid >> 5;

    {
        const size_t qoff = (size_t)(bt * NH + h) * SEQ * HD;
        const size_t koff = (size_t)(bt * NKV + kvh) * SEQ * HD;
        const __half* srcs[5] = {
            g_qt16 + qoff, g_k16h + koff, g_k16l + koff,
            g_v16h + koff, g_v16l + koff };
        #pragma unroll
        for (int t = 0; t < 5; t++) {
            const __half* s = srcs[t];
            const uint32_t dtile = sb + t * 32768;
            #pragma unroll
            for (int i = 0; i < 8; i++) {
                uint32_t q = tid + i * 256;
                uint32_t row = q >> 3, j = q & 7;
                cp16(dtile + ASW(row * 128 + j * 16), s + row * 64 + j * 8);
            }
        }
        asm volatile("cp.async.commit_group;" ::: "memory");
        asm volatile("cp.async.wait_group 0;" ::: "memory");
    }
    __syncthreads();

    const int qm = wid * 32;
    float acc[2][8][4];
    float rsum[2][2];
    #pragma unroll
    for (int i = 0; i < 2; i++) {
        rsum[i][0] = rsum[i][1] = 0.f;
        #pragma unroll
        for (int j = 0; j < 8; j++)
            #pragma unroll
            for (int e = 0; e < 4; e++) acc[i][j][e] = 0.f;
    }

    for (int kb = 0; kb < 4; kb++) {
        float S[2][8][4];
        #pragma unroll
        for (int i = 0; i < 2; i++)
            #pragma unroll
            for (int j = 0; j < 8; j++)
                #pragma unroll
                for (int e = 0; e < 4; e++) S[i][j][e] = 0.f;

        #pragma unroll
        for (int ks = 0; ks < 4; ks++) {
            uint32_t fQ[2][4];
            #pragma unroll
            for (int mt = 0; mt < 2; mt++) {
                uint32_t off = ASW((uint32_t)((qm + mt*16 + (lane & 15)) * 128
                              + ks * 32 + ((lane >> 4) & 1) * 16));
                ldmx4(fQ[mt], sQ + off);
            }
            uint32_t fKh[8][2], fKl[8][2];
            #pragma unroll
            for (int np = 0; np < 4; np++) {
                uint32_t krow = kb*64 + np*16 + (lane & 7) + ((lane >> 4) & 1) * 8;
                uint32_t off = ASW(krow * 128 + ks * 32 + ((lane >> 3) & 1) * 16);
                uint32_t t[4];
                ldmx4(t, sKh + off);
                fKh[2*np][0] = t[0]; fKh[2*np][1] = t[1];
                fKh[2*np+1][0] = t[2]; fKh[2*np+1][1] = t[3];
                ldmx4(t, sKl + off);
                fKl[2*np][0] = t[0]; fKl[2*np][1] = t[1];
                fKl[2*np+1][0] = t[2]; fKl[2*np+1][1] = t[3];
            }
            #pragma unroll
            for (int mt = 0; mt < 2; mt++)
                #pragma unroll
                for (int nt = 0; nt < 8; nt++) {
                    mma_fp(S[mt][nt], fQ[mt], fKh[nt]);
                    mma_fp(S[mt][nt], fQ[mt], fKl[nt]);
                }
        }

        uint32_t pA[2][4][4];
        #pragma unroll
        for (int mt = 0; mt < 2; mt++) {
            #pragma unroll
            for (int nt = 0; nt < 8; nt++) {
                #pragma unroll
                for (int e = 0; e < 4; e++)
                    S[mt][nt][e] = softcap_p(S[mt][nt][e]);
                rsum[mt][0] += S[mt][nt][0] + S[mt][nt][1];
                rsum[mt][1] += S[mt][nt][2] + S[mt][nt][3];
            }
            #pragma unroll
            for (int kk = 0; kk < 4; kk++) {
                __half2 p0 = __floats2half2_rn(S[mt][2*kk][0],   S[mt][2*kk][1]);
                __half2 p1 = __floats2half2_rn(S[mt][2*kk][2],   S[mt][2*kk][3]);
                __half2 p2 = __floats2half2_rn(S[mt][2*kk+1][0], S[mt][2*kk+1][1]);
                __half2 p3 = __floats2half2_rn(S[mt][2*kk+1][2], S[mt][2*kk+1][3]);
                pA[mt][kk][0] = *(uint32_t*)&p0;
                pA[mt][kk][1] = *(uint32_t*)&p1;
                pA[mt][kk][2] = *(uint32_t*)&p2;
                pA[mt][kk][3] = *(uint32_t*)&p3;
            }
        }

        #pragma unroll
        for (int kk = 0; kk < 4; kk++) {
            uint32_t fVh[8][2], fVl[8][2];
            #pragma unroll
            for (int np = 0; np < 4; np++) {
                uint32_t vrow = kb*64 + kk*16 + (lane & 7) + ((lane >> 3) & 1) * 8;
                uint32_t off = ASW(vrow * 128 + (np*16 + ((lane >> 4) & 1) * 8) * 2);
                uint32_t t[4];
                ldmx4t(t, sVh + off);
                fVh[2*np][0] = t[0]; fVh[2*np][1] = t[1];
                fVh[2*np+1][0] = t[2]; fVh[2*np+1][1] = t[3];
                ldmx4t(t, sVl + off);
                fVl[2*np][0] = t[0]; fVl[2*np][1] = t[1];
                fVl[2*np+1][0] = t[2]; fVl[2*np+1][1] = t[3];
            }
            #pragma unroll
            for (int mt = 0; mt < 2; mt++)
                #pragma unroll
                for (int nt = 0; nt < 8; nt++) {
                    mma_fp(acc[mt][nt], pA[mt][kk], fVh[nt]);
                    mma_fp(acc[mt][nt], pA[mt][kk], fVl[nt]);
                }
        }
    }

    #pragma unroll
    for (int mt = 0; mt < 2; mt++) {
        rsum[mt][0] += __shfl_xor_sync(0xffffffffu, rsum[mt][0], 1);
        rsum[mt][0] += __shfl_xor_sync(0xffffffffu, rsum[mt][0], 2);
        rsum[mt][1] += __shfl_xor_sync(0xffffffffu, rsum[mt][1], 1);
        rsum[mt][1] += __shfl_xor_sync(0xffffffffu, rsum[mt][1], 2);
    }
    #pragma unroll
    for (int mt = 0; mt < 2; mt++) {
        const float inv0 = 1.0f / rsum[mt][0];
        const float inv1 = 1.0f / rsum[mt][1];
        #pragma unroll
        for (int nt = 0; nt < 8; nt++) {
            int rq_ = qm + mt*16 + (lane >> 2);
            int col = nt*8 + (lane & 3) * 2;
            size_t o0 = (size_t)(bt * SEQ + rq_) * GK + h * HD + col;
            size_t o1 = o0 + (size_t)8 * GK;
            *(__half2*)(g_a16 + o0) =
                __floats2half2_rn(acc[mt][nt][0] * inv0, acc[mt][nt][1] * inv0);
            *(__half2*)(g_a16 + o1) =
                __floats2half2_rn(acc[mt][nt][2] * inv1, acc[mt][nt][3] * inv1);
        }
    }
}

// ---------------------------------------------------------------------------
// launch
// ---------------------------------------------------------------------------
extern "C" void kernel_launch(void* const* d_in, const int* in_sizes, int n_in,
                              void* d_out, int out_size)
{
    const float* x  = (const float*)d_in[0];
    const float* Wq = (const float*)d_in[1];
    const float* Wk = (const float*)d_in[2];
    const float* Wv = (const float*)d_in[3];
    const float* Wo = (const float*)d_in[4];
    const float* qw = (const float*)d_in[5];
    const float* kw = (const float*)d_in[6];
    float* out = (float*)d_out;

    static __half *x16 = nullptr, *a16, *w1h, *w1l, *w2h, *w2l;
    if (!x16) {
        cudaGetSymbolAddress((void**)&x16, g_x16);
        cudaGetSymbolAddress((void**)&a16, g_a16);
        cudaGetSymbolAddress((void**)&w1h, g_w1h);
        cudaGetSymbolAddress((void**)&w1l, g_w1l);
        cudaGetSymbolAddress((void**)&w2h, g_w2h);
        cudaGetSymbolAddress((void**)&w2l, g_w2l);
        cudaFuncSetAttribute(attn_mma,
                             cudaFuncAttributeMaxDynamicSharedMemorySize, ATT_SMEM);
        cudaFuncSetAttribute(gemm_mma<0>,
                             cudaFuncAttributeMaxDynamicSharedMemorySize, SMEM_GEMM);
        cudaFuncSetAttribute(gemm_mma<1>,
                             cudaFuncAttributeMaxDynamicSharedMemorySize, SMEM_GEMM);
    }

    const int n4 = MROWS * GK / 4;
    cvt_half<<<(n4 + 255) / 256, 256>>>(x, x16, n4);
    xpose_qkv<<<(QKVC * GK + 255) / 256, 256>>>(Wq, Wk, Wv, w1h, w1l);
    xpose_wo<<<(DIM * GK + 255) / 256, 256>>>(Wo, w2h, w2l);

    gemm_mma<1><<<dim3(QKVC / 128, MROWS / 128), 256, SMEM_GEMM>>>(
        x16, w1h, w1l, nullptr, 0, qw, kw);

    attn_mma<<<dim3(NH, BTN), 256, ATT_SMEM>>>();

    gemm_mma<0><<<dim3(DIM / 128, MROWS / 128), 256, SMEM_GEMM>>>(
        a16, w2h, w2l, out, DIM, nullptr, nullptr);
}

// round 15
// speedup vs baseline: 1.2988x; 1.1413x over previous
#include <cuda_runtime.h>
#include <cuda_bf16.h>
#include <cuda_fp16.h>
#include <math.h>
#include <stdint.h>

// Problem constants
#define BTN   128
#define SEQ   256
#define DIM   1024
#define NH    16
#define NKV   4
#define GRP   4
#define HD    64
#define MROWS (BTN*SEQ)      // 32768
#define QKVC  1536
#define GK    1024
#define EPSV  1e-6f
#define SCALEV 0.125f
#define CAPV  50.0f

// ---------------------------------------------------------------------------
// Scratch (device globals)
// ---------------------------------------------------------------------------
__device__ __align__(16) __half g_x16[(size_t)MROWS * GK];        // x as fp16
__device__ __align__(16) __half g_a16[(size_t)MROWS * GK];        // attn out fp16
__device__ __align__(16) __half g_w1h[(size_t)QKVC * GK];         // [n][k] hi
__device__ __align__(16) __half g_w1l[(size_t)QKVC * GK];         // [n][k] lo
__device__ __align__(16) __half g_w2h[(size_t)DIM * GK];          // Wo fp16 (single)
// attention tiles (fp16)
__device__ __align__(16) __half g_qt16[(size_t)MROWS * GK];       // Q tiles (single)
__device__ __align__(16) __half g_k16h[(size_t)MROWS * 256];      // K hi
__device__ __align__(16) __half g_k16l[(size_t)MROWS * 256];      // K lo
__device__ __align__(16) __half g_v16h[(size_t)MROWS * 256];      // V hi
__device__ __align__(16) __half g_v16l[(size_t)MROWS * 256];      // V lo

// ---------------------------------------------------------------------------
// helpers
// ---------------------------------------------------------------------------
__device__ __forceinline__ uint32_t smem_u32(const void* p) {
    uint32_t a;
    asm("{ .reg .u64 t; cvta.to.shared.u64 t, %1; cvt.u32.u64 %0, t; }"
        : "=r"(a) : "l"(p));
    return a;
}
__device__ __forceinline__ void cp16(uint32_t dst, const void* src) {
    asm volatile("cp.async.cg.shared.global [%0], [%1], 16;" :: "r"(dst), "l"(src));
}
__device__ __forceinline__ void ldmx4(uint32_t r[4], uint32_t addr) {
    asm volatile("ldmatrix.sync.aligned.m8n8.x4.shared.b16 {%0,%1,%2,%3}, [%4];"
                 : "=r"(r[0]), "=r"(r[1]), "=r"(r[2]), "=r"(r[3]) : "r"(addr));
}
__device__ __forceinline__ void ldmx4t(uint32_t r[4], uint32_t addr) {
    asm volatile("ldmatrix.sync.aligned.m8n8.x4.trans.shared.b16 {%0,%1,%2,%3}, [%4];"
                 : "=r"(r[0]), "=r"(r[1]), "=r"(r[2]), "=r"(r[3]) : "r"(addr));
}
__device__ __forceinline__ void mma_fp(float c[4], const uint32_t a[4],
                                       const uint32_t b[2]) {
    asm volatile("mma.sync.aligned.m16n8k16.row.col.f32.f16.f16.f32 "
                 "{%0,%1,%2,%3}, {%4,%5,%6,%7}, {%8,%9}, {%0,%1,%2,%3};"
                 : "+f"(c[0]), "+f"(c[1]), "+f"(c[2]), "+f"(c[3])
                 : "r"(a[0]), "r"(a[1]), "r"(a[2]), "r"(a[3]),
                   "r"(b[0]), "r"(b[1]));
}
__device__ __forceinline__ void split2h(float a, float b, uint32_t& H, uint32_t& L) {
    __half ah = __float2half_rn(a), bh = __float2half_rn(b);
    __half2 hh(ah, bh);
    H = *(uint32_t*)&hh;
    __half2 ll(__float2half_rn(a - __half2float(ah)),
               __float2half_rn(b - __half2float(bh)));
    L = *(uint32_t*)&ll;
}
// soft-capped softmax numerator, UNSHIFTED (constant cancels in normalization).
// Input y = z*SCALE (|y| <= 8).  p = exp(CAP*tanh(y/CAP)) in [e^-8, e^8].
__device__ __forceinline__ float softcap_p(float y) {
    float u = y * y;
    float t = fmaf(u, fmaf(u, fmaf(u, -3.4540e-12f, 2.1333334e-8f),
                            -1.3333334e-4f), 1.0f);
    float arg = (y * t) * 1.44269504f;
    float p;
    asm("ex2.approx.ftz.f32 %0, %1;" : "=f"(p) : "f"(arg));
    return p;
}
#define ASW(o) ((o) ^ (((o) >> 3) & 0x70))

// ---------------------------------------------------------------------------
// conversions
// ---------------------------------------------------------------------------
__global__ void cvt_half(const float* __restrict__ in,
                         __half* __restrict__ out, int n4)
{
    int i = blockIdx.x * blockDim.x + threadIdx.x;
    if (i >= n4) return;
    float4 v = ((const float4*)in)[i];
    __half2* op = (__half2*)out;
    op[2*i]   = __floats2half2_rn(v.x, v.y);
    op[2*i+1] = __floats2half2_rn(v.z, v.w);
}

__global__ void xpose_qkv(const float* __restrict__ Wq, const float* __restrict__ Wk,
                          const float* __restrict__ Wv,
                          __half* __restrict__ th, __half* __restrict__ tl)
{
    size_t idx = (size_t)blockIdx.x * blockDim.x + threadIdx.x;
    if (idx >= (size_t)QKVC * GK) return;
    int k = (int)(idx & (GK - 1));
    int n = (int)(idx >> 10);
    float v;
    if (n < DIM)            v = Wq[(size_t)k * (NH*HD)  + n];
    else if (n < DIM + 256) v = Wk[(size_t)k * (NKV*HD) + (n - DIM)];
    else                    v = Wv[(size_t)k * (NKV*HD) + (n - DIM - 256)];
    __half hv = __float2half_rn(v);
    th[idx] = hv;
    tl[idx] = __float2half_rn(v - __half2float(hv));
}

__global__ void xpose_wo(const float* __restrict__ W,
                         __half* __restrict__ th)
{
    size_t idx = (size_t)blockIdx.x * blockDim.x + threadIdx.x;
    if (idx >= (size_t)DIM * GK) return;
    int k = (int)(idx & (GK - 1));
    int n = (int)(idx >> 10);
    th[idx] = __float2half_rn(W[(size_t)k * DIM + n]);
}

// ---------------------------------------------------------------------------
// fp16 GEMM: C[m,n] = A[m,:].(Bh[n,:][+Bl[n,:]]),  K=1024
// 128x128 CTA tile, 8 warps (32x64 warp tiles), BK=64, 2-stage, SW128.
// NB = number of B terms (1 or 2).
// EPI=0: plain fp32 store.  EPI=1: QKV epilogue (rmsnorm fold + fp16 split).
// ---------------------------------------------------------------------------
#define BK      64
#define NCHUNK  (GK / BK)             // 16
#define TILE_B  (128 * 128)           // 16384
#define OFF_A   0
#define OFF_BH  TILE_B
#define OFF_BL  (2*TILE_B)
#define SMEM_G2 (2 * 3 * TILE_B + 1024)   // NB=2: 99328
#define SMEM_G1 (2 * 2 * TILE_B + 1024)   // NB=1: 66560

template<int NB>
__device__ __forceinline__ void g_load(uint32_t sbase, int tid,
    const __half* A, const __half* Bh, const __half* Bl, int koff)
{
    #pragma unroll
    for (int it = 0; it < 4; it++) {
        int g = tid + it * 256;
        int row = g >> 3;
        int j   = g & 7;
        uint32_t dst = sbase + ASW((uint32_t)(row * 128 + j * 16));
        size_t so = (size_t)row * GK + koff + j * 8;
        cp16(dst + OFF_A,  A  + so);
        cp16(dst + OFF_BH, Bh + so);
        if (NB == 2) cp16(dst + OFF_BL, Bl + so);
    }
    asm volatile("cp.async.commit_group;" ::: "memory");
}

template<int EPI, int NB>
__global__ void __launch_bounds__(256, 2)
gemm_mma(const __half* __restrict__ a, const __half* __restrict__ bh,
         const __half* __restrict__ bl, float* __restrict__ C, int ldc,
         const float* __restrict__ qw, const float* __restrict__ kw)
{
    constexpr uint32_t STGX = (uint32_t)(1 + NB) * TILE_B;
    extern __shared__ char smem_raw[];
    uint32_t sbr = smem_u32(smem_raw);
    const uint32_t sb = (sbr + 1023) & ~1023u;
    const int tid  = threadIdx.x;
    const int wid  = tid >> 5;
    const int lane = tid & 31;
    const int bm = blockIdx.y * 128;
    const int bn = blockIdx.x * 128;

    const __half* A  = a  + (size_t)bm * GK;
    const __half* Bh = bh + (size_t)bn * GK;
    const __half* Bl = (NB == 2) ? bl + (size_t)bn * GK : nullptr;

    const int wm = (wid & 3) * 32;
    const int wn = (wid >> 2) * 64;
    const int ar = lane & 15;
    const int ac = (lane >> 4) * 16;
    const int br = (lane & 7) + ((lane >> 4) & 1) * 8;
    const int bc = ((lane >> 3) & 1) * 16;

    float acc[2][8][4];
    #pragma unroll
    for (int i = 0; i < 2; i++)
        #pragma unroll
        for (int j = 0; j < 8; j++)
            #pragma unroll
            for (int e = 0; e < 4; e++) acc[i][j][e] = 0.f;

    g_load<NB>(sb, tid, A, Bh, Bl, 0);

    for (int c = 0; c < NCHUNK; c++) {
        asm volatile("cp.async.wait_group 0;" ::: "memory");
        __syncthreads();
        if (c + 1 < NCHUNK)
            g_load<NB>(sb + ((c + 1) & 1) * STGX, tid, A, Bh, Bl, (c + 1) * BK);

        const uint32_t st = sb + (c & 1) * STGX;
        #pragma unroll
        for (int kk = 0; kk < 4; kk++) {
            const int kb = kk * 32;
            uint32_t fA[2][4];
            #pragma unroll
            for (int mt = 0; mt < 2; mt++) {
                uint32_t off = ASW((uint32_t)((wm + mt * 16 + ar) * 128 + kb + ac));
                ldmx4(fA[mt], st + OFF_A + off);
            }
            uint32_t fBh[8][2], fBl[8][2];
            #pragma unroll
            for (int g = 0; g < 4; g++) {
                uint32_t off = ASW((uint32_t)((wn + g * 16 + br) * 128 + kb + bc));
                uint32_t t[4];
                ldmx4(t, st + OFF_BH + off);
                fBh[2*g][0] = t[0]; fBh[2*g][1] = t[1];
                fBh[2*g+1][0] = t[2]; fBh[2*g+1][1] = t[3];
                if (NB == 2) {
                    ldmx4(t, st + OFF_BL + off);
                    fBl[2*g][0] = t[0]; fBl[2*g][1] = t[1];
                    fBl[2*g+1][0] = t[2]; fBl[2*g+1][1] = t[3];
                }
            }
            #pragma unroll
            for (int mt = 0; mt < 2; mt++)
                #pragma unroll
                for (int nt = 0; nt < 8; nt++) {
                    mma_fp(acc[mt][nt], fA[mt], fBh[nt]);
                    if (NB == 2) mma_fp(acc[mt][nt], fA[mt], fBl[nt]);
                }
        }
    }

    const int er = lane >> 2;
    const int ec = (lane & 3) * 2;

    if (EPI == 0) {
        #pragma unroll
        for (int mt = 0; mt < 2; mt++)
            #pragma unroll
            for (int nt = 0; nt < 8; nt++) {
                size_t row0 = (size_t)(bm + wm + mt * 16 + er) * ldc
                            + bn + wn + nt * 8 + ec;
                *(float2*)&C[row0]           = make_float2(acc[mt][nt][0], acc[mt][nt][1]);
                *(float2*)&C[row0 + 8 * ldc] = make_float2(acc[mt][nt][2], acc[mt][nt][3]);
            }
        return;
    }

    // ---- EPI == 1: QKV epilogue, rmsnorm fold + fp16 tile writes ----
    const int gn = bn + wn;
    float wqk[16];
    if (gn < DIM) {
        #pragma unroll
        for (int nt = 0; nt < 8; nt++) {
            int col = nt * 8 + ec;
            wqk[2*nt]   = __ldg(&qw[col])   * __ldg(&kw[col]);
            wqk[2*nt+1] = __ldg(&qw[col+1]) * __ldg(&kw[col+1]);
        }
    }

    #pragma unroll
    for (int mt = 0; mt < 2; mt++) {
        #pragma unroll
        for (int hf = 0; hf < 2; hf++) {
            const int grow = bm + wm + mt * 16 + er + hf * 8;
            const int bt = grow >> 8;
            const int s  = grow & 255;
            float v[16];
            #pragma unroll
            for (int nt = 0; nt < 8; nt++) {
                v[2*nt]   = acc[mt][nt][hf*2];
                v[2*nt+1] = acc[mt][nt][hf*2+1];
            }
            if (gn < DIM) {                    // Q
                float ssq = 0.f;
                #pragma unroll
                for (int j = 0; j < 16; j++) ssq += v[j] * v[j];
                ssq += __shfl_xor_sync(0xffffffffu, ssq, 1);
                ssq += __shfl_xor_sync(0xffffffffu, ssq, 2);
                float r = rsqrtf(ssq * (1.0f / HD) + EPSV) * SCALEV;
                int h = gn >> 6;
                size_t dbase = ((size_t)(bt * NH + h) * SEQ + s) * HD;
                #pragma unroll
                for (int nt = 0; nt < 8; nt++) {
                    __half2 hp = __floats2half2_rn(v[2*nt] * r * wqk[2*nt],
                                                   v[2*nt+1] * r * wqk[2*nt+1]);
                    *(__half2*)(g_qt16 + dbase + nt * 8 + ec) = hp;
                }
            } else if (gn < DIM + 256) {       // K
                float ssq = 0.f;
                #pragma unroll
                for (int j = 0; j < 16; j++) ssq += v[j] * v[j];
                ssq += __shfl_xor_sync(0xffffffffu, ssq, 1);
                ssq += __shfl_xor_sync(0xffffffffu, ssq, 2);
                float r = rsqrtf(ssq * (1.0f / HD) + EPSV);
                int kvh = (gn - DIM) >> 6;
                size_t dbase = ((size_t)(bt * NKV + kvh) * SEQ + s) * HD;
                #pragma unroll
                for (int nt = 0; nt < 8; nt++) {
                    uint32_t H, L;
                    split2h(v[2*nt] * r, v[2*nt+1] * r, H, L);
                    *(uint32_t*)(g_k16h + dbase + nt * 8 + ec) = H;
                    *(uint32_t*)(g_k16l + dbase + nt * 8 + ec) = L;
                }
            } else {                            // V
                int kvh = (gn - DIM - 256) >> 6;
                size_t dbase = ((size_t)(bt * NKV + kvh) * SEQ + s) * HD;
                #pragma unroll
                for (int nt = 0; nt < 8; nt++) {
                    uint32_t H, L;
                    split2h(v[2*nt], v[2*nt+1], H, L);
                    *(uint32_t*)(g_v16h + dbase + nt * 8 + ec) = H;
                    *(uint32_t*)(g_v16l + dbase + nt * 8 + ec) = L;
                }
            }
        }
    }
}

// ---------------------------------------------------------------------------
// Tensor-core attention: block per (bt, h), 256 threads (8 warps).
// Q single fp16, K fp16 hi/lo, P single fp16 (unshifted), V fp16 hi/lo.
// ---------------------------------------------------------------------------
#define ATT_SMEM (5 * 32768 + 1024)

__global__ void __launch_bounds__(256, 1)
attn_mma()
{
    extern __shared__ char smem_raw[];
    uint32_t sbr = smem_u32(smem_raw);
    const uint32_t sb = (sbr + 1023) & ~1023u;
    const uint32_t sQ = sb, sKh = sb + 32768, sKl = sb + 65536,
                   sVh = sb + 98304, sVl = sb + 131072;

    const int h  = blockIdx.x;
    const int bt = blockIdx.y;
    const int kvh = h >> 2;
    const int tid = threadIdx.x;
    const int lane = tid & 31;
    const int wid = tid >> 5;

    {
        const size_t qoff = (size_t)(bt * NH + h) * SEQ * HD;
        const size_t koff = (size_t)(bt * NKV + kvh) * SEQ * HD;
        const __half* srcs[5] = {
            g_qt16 + qoff, g_k16h + koff, g_k16l + koff,
            g_v16h + koff, g_v16l + koff };
        #pragma unroll
        for (int t = 0; t < 5; t++) {
            const __half* s = srcs[t];
            const uint32_t dtile = sb + t * 32768;
            #pragma unroll
            for (int i = 0; i < 8; i++) {
                uint32_t q = tid + i * 256;
                uint32_t row = q >> 3, j = q & 7;
                cp16(dtile + ASW(row * 128 + j * 16), s + row * 64 + j * 8);
            }
        }
        asm volatile("cp.async.commit_group;" ::: "memory");
        asm volatile("cp.async.wait_group 0;" ::: "memory");
    }
    __syncthreads();

    const int qm = wid * 32;
    float acc[2][8][4];
    float rsum[2][2];
    #pragma unroll
    for (int i = 0; i < 2; i++) {
        rsum[i][0] = rsum[i][1] = 0.f;
        #pragma unroll
        for (int j = 0; j < 8; j++)
            #pragma unroll
            for (int e = 0; e < 4; e++) acc[i][j][e] = 0.f;
    }

    for (int kb = 0; kb < 4; kb++) {
        float S[2][8][4];
        #pragma unroll
        for (int i = 0; i < 2; i++)
            #pragma unroll
            for (int j = 0; j < 8; j++)
                #pragma unroll
                for (int e = 0; e < 4; e++) S[i][j][e] = 0.f;

        #pragma unroll
        for (int ks = 0; ks < 4; ks++) {
            uint32_t fQ[2][4];
            #pragma unroll
            for (int mt = 0; mt < 2; mt++) {
                uint32_t off = ASW((uint32_t)((qm + mt*16 + (lane & 15)) * 128
                              + ks * 32 + ((lane >> 4) & 1) * 16));
                ldmx4(fQ[mt], sQ + off);
            }
            uint32_t fKh[8][2], fKl[8][2];
            #pragma unroll
            for (int np = 0; np < 4; np++) {
                uint32_t krow = kb*64 + np*16 + (lane & 7) + ((lane >> 4) & 1) * 8;
                uint32_t off = ASW(krow * 128 + ks * 32 + ((lane >> 3) & 1) * 16);
                uint32_t t[4];
                ldmx4(t, sKh + off);
                fKh[2*np][0] = t[0]; fKh[2*np][1] = t[1];
                fKh[2*np+1][0] = t[2]; fKh[2*np+1][1] = t[3];
                ldmx4(t, sKl + off);
                fKl[2*np][0] = t[0]; fKl[2*np][1] = t[1];
                fKl[2*np+1][0] = t[2]; fKl[2*np+1][1] = t[3];
            }
            #pragma unroll
            for (int mt = 0; mt < 2; mt++)
                #pragma unroll
                for (int nt = 0; nt < 8; nt++) {
                    mma_fp(S[mt][nt], fQ[mt], fKh[nt]);
                    mma_fp(S[mt][nt], fQ[mt], fKl[nt]);
                }
        }

        uint32_t pA[2][4][4];
        #pragma unroll
        for (int mt = 0; mt < 2; mt++) {
            #pragma unroll
            for (int nt = 0; nt < 8; nt++) {
                #pragma unroll
                for (int e = 0; e < 4; e++)
                    S[mt][nt][e] = softcap_p(S[mt][nt][e]);
                rsum[mt][0] += S[mt][nt][0] + S[mt][nt][1];
                rsum[mt][1] += S[mt][nt][2] + S[mt][nt][3];
            }
            #pragma unroll
            for (int kk = 0; kk < 4; kk++) {
                __half2 p0 = __floats2half2_rn(S[mt][2*kk][0],   S[mt][2*kk][1]);
                __half2 p1 = __floats2half2_rn(S[mt][2*kk][2],   S[mt][2*kk][3]);
                __half2 p2 = __floats2half2_rn(S[mt][2*kk+1][0], S[mt][2*kk+1][1]);
                __half2 p3 = __floats2half2_rn(S[mt][2*kk+1][2], S[mt][2*kk+1][3]);
                pA[mt][kk][0] = *(uint32_t*)&p0;
                pA[mt][kk][1] = *(uint32_t*)&p1;
                pA[mt][kk][2] = *(uint32_t*)&p2;
                pA[mt][kk][3] = *(uint32_t*)&p3;
            }
        }

        #pragma unroll
        for (int kk = 0; kk < 4; kk++) {
            uint32_t fVh[8][2], fVl[8][2];
            #pragma unroll
            for (int np = 0; np < 4; np++) {
                uint32_t vrow = kb*64 + kk*16 + (lane & 7) + ((lane >> 3) & 1) * 8;
                uint32_t off = ASW(vrow * 128 + (np*16 + ((lane >> 4) & 1) * 8) * 2);
                uint32_t t[4];
                ldmx4t(t, sVh + off);
                fVh[2*np][0] = t[0]; fVh[2*np][1] = t[1];
                fVh[2*np+1][0] = t[2]; fVh[2*np+1][1] = t[3];
                ldmx4t(t, sVl + off);
                fVl[2*np][0] = t[0]; fVl[2*np][1] = t[1];
                fVl[2*np+1][0] = t[2]; fVl[2*np+1][1] = t[3];
            }
            #pragma unroll
            for (int mt = 0; mt < 2; mt++)
                #pragma unroll
                for (int nt = 0; nt < 8; nt++) {
                    mma_fp(acc[mt][nt], pA[mt][kk], fVh[nt]);
                    mma_fp(acc[mt][nt], pA[mt][kk], fVl[nt]);
                }
        }
    }

    #pragma unroll
    for (int mt = 0; mt < 2; mt++) {
        rsum[mt][0] += __shfl_xor_sync(0xffffffffu, rsum[mt][0], 1);
        rsum[mt][0] += __shfl_xor_sync(0xffffffffu, rsum[mt][0], 2);
        rsum[mt][1] += __shfl_xor_sync(0xffffffffu, rsum[mt][1], 1);
        rsum[mt][1] += __shfl_xor_sync(0xffffffffu, rsum[mt][1], 2);
    }
    #pragma unroll
    for (int mt = 0; mt < 2; mt++) {
        const float inv0 = 1.0f / rsum[mt][0];
        const float inv1 = 1.0f / rsum[mt][1];
        #pragma unroll
        for (int nt = 0; nt < 8; nt++) {
            int rq_ = qm + mt*16 + (lane >> 2);
            int col = nt*8 + (lane & 3) * 2;
            size_t o0 = (size_t)(bt * SEQ + rq_) * GK + h * HD + col;
            size_t o1 = o0 + (size_t)8 * GK;
            *(__half2*)(g_a16 + o0) =
                __floats2half2_rn(acc[mt][nt][0] * inv0, acc[mt][nt][1] * inv0);
            *(__half2*)(g_a16 + o1) =
                __floats2half2_rn(acc[mt][nt][2] * inv1, acc[mt][nt][3] * inv1);
        }
    }
}

// ---------------------------------------------------------------------------
// launch
// ---------------------------------------------------------------------------
extern "C" void kernel_launch(void* const* d_in, const int* in_sizes, int n_in,
                              void* d_out, int out_size)
{
    const float* x  = (const float*)d_in[0];
    const float* Wq = (const float*)d_in[1];
    const float* Wk = (const float*)d_in[2];
    const float* Wv = (const float*)d_in[3];
    const float* Wo = (const float*)d_in[4];
    const float* qw = (const float*)d_in[5];
    const float* kw = (const float*)d_in[6];
    float* out = (float*)d_out;

    static __half *x16 = nullptr, *a16, *w1h, *w1l, *w2h;
    if (!x16) {
        cudaGetSymbolAddress((void**)&x16, g_x16);
        cudaGetSymbolAddress((void**)&a16, g_a16);
        cudaGetSymbolAddress((void**)&w1h, g_w1h);
        cudaGetSymbolAddress((void**)&w1l, g_w1l);
        cudaGetSymbolAddress((void**)&w2h, g_w2h);
        cudaFuncSetAttribute(attn_mma,
                             cudaFuncAttributeMaxDynamicSharedMemorySize, ATT_SMEM);
        cudaFuncSetAttribute((const void*)gemm_mma<1, 2>,
                             cudaFuncAttributeMaxDynamicSharedMemorySize, SMEM_G2);
        cudaFuncSetAttribute((const void*)gemm_mma<0, 1>,
                             cudaFuncAttributeMaxDynamicSharedMemorySize, SMEM_G1);
    }

    const int n4 = MROWS * GK / 4;
    cvt_half<<<(n4 + 255) / 256, 256>>>(x, x16, n4);
    xpose_qkv<<<(QKVC * GK + 255) / 256, 256>>>(Wq, Wk, Wv, w1h, w1l);
    xpose_wo<<<(DIM * GK + 255) / 256, 256>>>(Wo, w2h);

    gemm_mma<1, 2><<<dim3(QKVC / 128, MROWS / 128), 256, SMEM_G2>>>(
        x16, w1h, w1l, nullptr, 0, qw, kw);

    attn_mma<<<dim3(NH, BTN), 256, ATT_SMEM>>>();

    gemm_mma<0, 1><<<dim3(DIM / 128, MROWS / 128), 256, SMEM_G1>>>(
        a16, w2h, nullptr, out, DIM, nullptr, nullptr);
}

// round 16
// speedup vs baseline: 1.4986x; 1.1538x over previous
#include <cuda_runtime.h>
#include <cuda_bf16.h>
#include <cuda_fp16.h>
#include <math.h>
#include <stdint.h>

// Problem constants
#define BTN   128
#define SEQ   256
#define DIM   1024
#define NH    16
#define NKV   4
#define GRP   4
#define HD    64
#define MROWS (BTN*SEQ)      // 32768
#define QKVC  1536
#define GK    1024
#define EPSV  1e-6f
#define SCALEV 0.125f
#define CAPV  50.0f

// ---------------------------------------------------------------------------
// Scratch (device globals)
// ---------------------------------------------------------------------------
__device__ __align__(16) __half g_x16[(size_t)MROWS * GK];        // x as fp16
__device__ __align__(16) __half g_a16[(size_t)MROWS * GK];        // attn out fp16
__device__ __align__(16) __half g_w1h[(size_t)QKVC * GK];         // [n][k] hi
__device__ __align__(16) __half g_w1l[(size_t)QKVC * GK];         // [n][k] lo
__device__ __align__(16) __half g_w2h[(size_t)DIM * GK];          // Wo fp16 (single)
// attention tiles (fp16)
__device__ __align__(16) __half g_qt16[(size_t)MROWS * GK];       // Q tiles (single)
__device__ __align__(16) __half g_k16h[(size_t)MROWS * 256];      // K hi
__device__ __align__(16) __half g_k16l[(size_t)MROWS * 256];      // K lo
__device__ __align__(16) __half g_v16h[(size_t)MROWS * 256];      // V hi
__device__ __align__(16) __half g_v16l[(size_t)MROWS * 256];      // V lo

// ---------------------------------------------------------------------------
// helpers
// ---------------------------------------------------------------------------
__device__ __forceinline__ uint32_t smem_u32(const void* p) {
    uint32_t a;
    asm("{ .reg .u64 t; cvta.to.shared.u64 t, %1; cvt.u32.u64 %0, t; }"
        : "=r"(a) : "l"(p));
    return a;
}
__device__ __forceinline__ void cp16(uint32_t dst, const void* src) {
    asm volatile("cp.async.cg.shared.global [%0], [%1], 16;" :: "r"(dst), "l"(src));
}
__device__ __forceinline__ void ldmx4(uint32_t r[4], uint32_t addr) {
    asm volatile("ldmatrix.sync.aligned.m8n8.x4.shared.b16 {%0,%1,%2,%3}, [%4];"
                 : "=r"(r[0]), "=r"(r[1]), "=r"(r[2]), "=r"(r[3]) : "r"(addr));
}
__device__ __forceinline__ void ldmx4t(uint32_t r[4], uint32_t addr) {
    asm volatile("ldmatrix.sync.aligned.m8n8.x4.trans.shared.b16 {%0,%1,%2,%3}, [%4];"
                 : "=r"(r[0]), "=r"(r[1]), "=r"(r[2]), "=r"(r[3]) : "r"(addr));
}
__device__ __forceinline__ void mma_fp(float c[4], const uint32_t a[4],
                                       const uint32_t b[2]) {
    asm volatile("mma.sync.aligned.m16n8k16.row.col.f32.f16.f16.f32 "
                 "{%0,%1,%2,%3}, {%4,%5,%6,%7}, {%8,%9}, {%0,%1,%2,%3};"
                 : "+f"(c[0]), "+f"(c[1]), "+f"(c[2]), "+f"(c[3])
                 : "r"(a[0]), "r"(a[1]), "r"(a[2]), "r"(a[3]),
                   "r"(b[0]), "r"(b[1]));
}
__device__ __forceinline__ void split2h(float a, float b, uint32_t& H, uint32_t& L) {
    __half ah = __float2half_rn(a), bh = __float2half_rn(b);
    __half2 hh(ah, bh);
    H = *(uint32_t*)&hh;
    __half2 ll(__float2half_rn(a - __half2float(ah)),
               __float2half_rn(b - __half2float(bh)));
    L = *(uint32_t*)&ll;
}
// soft-capped softmax numerator, UNSHIFTED (constant cancels in normalization).
// Input y = z*SCALE (|y| <= 8).  p = exp(CAP*tanh(y/CAP)) in [e^-8, e^8].
__device__ __forceinline__ float softcap_p(float y) {
    float u = y * y;
    float t = fmaf(u, fmaf(u, fmaf(u, -3.4540e-12f, 2.1333334e-8f),
                            -1.3333334e-4f), 1.0f);
    float arg = (y * t) * 1.44269504f;
    float p;
    asm("ex2.approx.ftz.f32 %0, %1;" : "=f"(p) : "f"(arg));
    return p;
}
#define ASW(o) ((o) ^ (((o) >> 3) & 0x70))

// ---------------------------------------------------------------------------
// conversions
// ---------------------------------------------------------------------------
__global__ void cvt_half(const float* __restrict__ in,
                         __half* __restrict__ out, int n4)
{
    int i = blockIdx.x * blockDim.x + threadIdx.x;
    if (i >= n4) return;
    float4 v = ((const float4*)in)[i];
    __half2* op = (__half2*)out;
    op[2*i]   = __floats2half2_rn(v.x, v.y);
    op[2*i+1] = __floats2half2_rn(v.z, v.w);
}

__global__ void xpose_qkv(const float* __restrict__ Wq, const float* __restrict__ Wk,
                          const float* __restrict__ Wv,
                          __half* __restrict__ th, __half* __restrict__ tl)
{
    size_t idx = (size_t)blockIdx.x * blockDim.x + threadIdx.x;
    if (idx >= (size_t)QKVC * GK) return;
    int k = (int)(idx & (GK - 1));
    int n = (int)(idx >> 10);
    float v;
    if (n < DIM)            v = Wq[(size_t)k * (NH*HD)  + n];
    else if (n < DIM + 256) v = Wk[(size_t)k * (NKV*HD) + (n - DIM)];
    else                    v = Wv[(size_t)k * (NKV*HD) + (n - DIM - 256)];
    __half hv = __float2half_rn(v);
    th[idx] = hv;
    tl[idx] = __float2half_rn(v - __half2float(hv));
}

__global__ void xpose_wo(const float* __restrict__ W,
                         __half* __restrict__ th)
{
    size_t idx = (size_t)blockIdx.x * blockDim.x + threadIdx.x;
    if (idx >= (size_t)DIM * GK) return;
    int k = (int)(idx & (GK - 1));
    int n = (int)(idx >> 10);
    th[idx] = __float2half_rn(W[(size_t)k * DIM + n]);
}

// ---------------------------------------------------------------------------
// fp16 GEMM: C[m,n] = A[m,:].(Bh[n,:][+Bl[n,:]]),  K=1024
// 128x128 CTA tile, 8 warps (32x64 warp tiles), BK=64, 2-stage, SW128.
// NB = number of B terms (1 or 2).  gnoff = global n offset of this launch.
// EPI=0: plain fp32 store.  EPI=1: QKV epilogue (rmsnorm fold + fp16 split).
// ---------------------------------------------------------------------------
#define BK      64
#define NCHUNK  (GK / BK)             // 16
#define TILE_B  (128 * 128)           // 16384
#define OFF_A   0
#define OFF_BH  TILE_B
#define OFF_BL  (2*TILE_B)
#define SMEM_G2 (2 * 3 * TILE_B + 1024)   // NB=2: 99328
#define SMEM_G1 (2 * 2 * TILE_B + 1024)   // NB=1: 66560

template<int NB>
__device__ __forceinline__ void g_load(uint32_t sbase, int tid,
    const __half* A, const __half* Bh, const __half* Bl, int koff)
{
    #pragma unroll
    for (int it = 0; it < 4; it++) {
        int g = tid + it * 256;
        int row = g >> 3;
        int j   = g & 7;
        uint32_t dst = sbase + ASW((uint32_t)(row * 128 + j * 16));
        size_t so = (size_t)row * GK + koff + j * 8;
        cp16(dst + OFF_A,  A  + so);
        cp16(dst + OFF_BH, Bh + so);
        if (NB == 2) cp16(dst + OFF_BL, Bl + so);
    }
    asm volatile("cp.async.commit_group;" ::: "memory");
}

template<int EPI, int NB>
__global__ void __launch_bounds__(256, 2)
gemm_mma(const __half* __restrict__ a, const __half* __restrict__ bh,
         const __half* __restrict__ bl, float* __restrict__ C, int ldc,
         const float* __restrict__ qw, const float* __restrict__ kw, int gnoff)
{
    constexpr uint32_t STGX = (uint32_t)(1 + NB) * TILE_B;
    extern __shared__ char smem_raw[];
    uint32_t sbr = smem_u32(smem_raw);
    const uint32_t sb = (sbr + 1023) & ~1023u;
    const int tid  = threadIdx.x;
    const int wid  = tid >> 5;
    const int lane = tid & 31;
    const int bm = blockIdx.y * 128;
    const int bn = blockIdx.x * 128;

    const __half* A  = a  + (size_t)bm * GK;
    const __half* Bh = bh + (size_t)bn * GK;
    const __half* Bl = (NB == 2) ? bl + (size_t)bn * GK : nullptr;

    const int wm = (wid & 3) * 32;
    const int wn = (wid >> 2) * 64;
    const int ar = lane & 15;
    const int ac = (lane >> 4) * 16;
    const int br = (lane & 7) + ((lane >> 4) & 1) * 8;
    const int bc = ((lane >> 3) & 1) * 16;

    float acc[2][8][4];
    #pragma unroll
    for (int i = 0; i < 2; i++)
        #pragma unroll
        for (int j = 0; j < 8; j++)
            #pragma unroll
            for (int e = 0; e < 4; e++) acc[i][j][e] = 0.f;

    g_load<NB>(sb, tid, A, Bh, Bl, 0);

    for (int c = 0; c < NCHUNK; c++) {
        asm volatile("cp.async.wait_group 0;" ::: "memory");
        __syncthreads();
        if (c + 1 < NCHUNK)
            g_load<NB>(sb + ((c + 1) & 1) * STGX, tid, A, Bh, Bl, (c + 1) * BK);

        const uint32_t st = sb + (c & 1) * STGX;
        #pragma unroll
        for (int kk = 0; kk < 4; kk++) {
            const int kb = kk * 32;
            uint32_t fA[2][4];
            #pragma unroll
            for (int mt = 0; mt < 2; mt++) {
                uint32_t off = ASW((uint32_t)((wm + mt * 16 + ar) * 128 + kb + ac));
                ldmx4(fA[mt], st + OFF_A + off);
            }
            uint32_t fBh[8][2], fBl[8][2];
            #pragma unroll
            for (int g = 0; g < 4; g++) {
                uint32_t off = ASW((uint32_t)((wn + g * 16 + br) * 128 + kb + bc));
                uint32_t t[4];
                ldmx4(t, st + OFF_BH + off);
                fBh[2*g][0] = t[0]; fBh[2*g][1] = t[1];
                fBh[2*g+1][0] = t[2]; fBh[2*g+1][1] = t[3];
                if (NB == 2) {
                    ldmx4(t, st + OFF_BL + off);
                    fBl[2*g][0] = t[0]; fBl[2*g][1] = t[1];
                    fBl[2*g+1][0] = t[2]; fBl[2*g+1][1] = t[3];
                }
            }
            #pragma unroll
            for (int mt = 0; mt < 2; mt++)
                #pragma unroll
                for (int nt = 0; nt < 8; nt++) {
                    mma_fp(acc[mt][nt], fA[mt], fBh[nt]);
                    if (NB == 2) mma_fp(acc[mt][nt], fA[mt], fBl[nt]);
                }
        }
    }

    const int er = lane >> 2;
    const int ec = (lane & 3) * 2;

    if (EPI == 0) {
        #pragma unroll
        for (int mt = 0; mt < 2; mt++)
            #pragma unroll
            for (int nt = 0; nt < 8; nt++) {
                size_t row0 = (size_t)(bm + wm + mt * 16 + er) * ldc
                            + bn + wn + nt * 8 + ec;
                *(float2*)&C[row0]           = make_float2(acc[mt][nt][0], acc[mt][nt][1]);
                *(float2*)&C[row0 + 8 * ldc] = make_float2(acc[mt][nt][2], acc[mt][nt][3]);
            }
        return;
    }

    // ---- EPI == 1: QKV epilogue, rmsnorm fold + fp16 tile writes ----
    const int gn = gnoff + bn + wn;    // global n (head-aligned, multiple of 64)
    float wqk[16];
    if (gn < DIM) {
        #pragma unroll
        for (int nt = 0; nt < 8; nt++) {
            int col = nt * 8 + ec;
            wqk[2*nt]   = __ldg(&qw[col])   * __ldg(&kw[col]);
            wqk[2*nt+1] = __ldg(&qw[col+1]) * __ldg(&kw[col+1]);
        }
    }

    #pragma unroll
    for (int mt = 0; mt < 2; mt++) {
        #pragma unroll
        for (int hf = 0; hf < 2; hf++) {
            const int grow = bm + wm + mt * 16 + er + hf * 8;
            const int bt = grow >> 8;
            const int s  = grow & 255;
            float v[16];
            #pragma unroll
            for (int nt = 0; nt < 8; nt++) {
                v[2*nt]   = acc[mt][nt][hf*2];
                v[2*nt+1] = acc[mt][nt][hf*2+1];
            }
            if (gn < DIM) {                    // Q
                float ssq = 0.f;
                #pragma unroll
                for (int j = 0; j < 16; j++) ssq += v[j] * v[j];
                ssq += __shfl_xor_sync(0xffffffffu, ssq, 1);
                ssq += __shfl_xor_sync(0xffffffffu, ssq, 2);
                float r = rsqrtf(ssq * (1.0f / HD) + EPSV) * SCALEV;
                int h = gn >> 6;
                size_t dbase = ((size_t)(bt * NH + h) * SEQ + s) * HD;
                #pragma unroll
                for (int nt = 0; nt < 8; nt++) {
                    __half2 hp = __floats2half2_rn(v[2*nt] * r * wqk[2*nt],
                                                   v[2*nt+1] * r * wqk[2*nt+1]);
                    *(__half2*)(g_qt16 + dbase + nt * 8 + ec) = hp;
                }
            } else if (gn < DIM + 256) {       // K
                float ssq = 0.f;
                #pragma unroll
                for (int j = 0; j < 16; j++) ssq += v[j] * v[j];
                ssq += __shfl_xor_sync(0xffffffffu, ssq, 1);
                ssq += __shfl_xor_sync(0xffffffffu, ssq, 2);
                float r = rsqrtf(ssq * (1.0f / HD) + EPSV);
                int kvh = (gn - DIM) >> 6;
                size_t dbase = ((size_t)(bt * NKV + kvh) * SEQ + s) * HD;
                #pragma unroll
                for (int nt = 0; nt < 8; nt++) {
                    uint32_t H, L;
                    split2h(v[2*nt] * r, v[2*nt+1] * r, H, L);
                    *(uint32_t*)(g_k16h + dbase + nt * 8 + ec) = H;
                    *(uint32_t*)(g_k16l + dbase + nt * 8 + ec) = L;
                }
            } else {                            // V
                int kvh = (gn - DIM - 256) >> 6;
                size_t dbase = ((size_t)(bt * NKV + kvh) * SEQ + s) * HD;
                #pragma unroll
                for (int nt = 0; nt < 8; nt++) {
                    uint32_t H, L;
                    split2h(v[2*nt], v[2*nt+1], H, L);
                    *(uint32_t*)(g_v16h + dbase + nt * 8 + ec) = H;
                    *(uint32_t*)(g_v16l + dbase + nt * 8 + ec) = L;
                }
            }
        }
    }
}

// ---------------------------------------------------------------------------
// Tensor-core attention: block per (bt, h), 256 threads (8 warps).
// Q single fp16, K fp16 hi/lo, P single fp16 (unshifted), V fp16 hi/lo.
// ---------------------------------------------------------------------------
#define ATT_SMEM (5 * 32768 + 1024)

__global__ void __launch_bounds__(256, 1)
attn_mma()
{
    extern __shared__ char smem_raw[];
    uint32_t sbr = smem_u32(smem_raw);
    const uint32_t sb = (sbr + 1023) & ~1023u;
    const uint32_t sQ = sb, sKh = sb + 32768, sKl = sb + 65536,
                   sVh = sb + 98304, sVl = sb + 131072;

    const int h  = blockIdx.x;
    const int bt = blockIdx.y;
    const int kvh = h >> 2;
    const int tid = threadIdx.x;
    const int lane = tid & 31;
    const int wid = tid >> 5;

    {
        const size_t qoff = (size_t)(bt * NH + h) * SEQ * HD;
        const size_t koff = (size_t)(bt * NKV + kvh) * SEQ * HD;
        const __half* srcs[5] = {
            g_qt16 + qoff, g_k16h + koff, g_k16l + koff,
            g_v16h + koff, g_v16l + koff };
        #pragma unroll
        for (int t = 0; t < 5; t++) {
            const __half* s = srcs[t];
            const uint32_t dtile = sb + t * 32768;
            #pragma unroll
            for (int i = 0; i < 8; i++) {
                uint32_t q = tid + i * 256;
                uint32_t row = q >> 3, j = q & 7;
                cp16(dtile + ASW(row * 128 + j * 16), s + row * 64 + j * 8);
            }
        }
        asm volatile("cp.async.commit_group;" ::: "memory");
        asm volatile("cp.async.wait_group 0;" ::: "memory");
    }
    __syncthreads();

    const int qm = wid * 32;
    float acc[2][8][4];
    float rsum[2][2];
    #pragma unroll
    for (int i = 0; i < 2; i++) {
        rsum[i][0] = rsum[i][1] = 0.f;
        #pragma unroll
        for (int j = 0; j < 8; j++)
            #pragma unroll
            for (int e = 0; e < 4; e++) acc[i][j][e] = 0.f;
    }

    for (int kb = 0; kb < 4; kb++) {
        float S[2][8][4];
        #pragma unroll
        for (int i = 0; i < 2; i++)
            #pragma unroll
            for (int j = 0; j < 8; j++)
                #pragma unroll
                for (int e = 0; e < 4; e++) S[i][j][e] = 0.f;

        #pragma unroll
        for (int ks = 0; ks < 4; ks++) {
            uint32_t fQ[2][4];
            #pragma unroll
            for (int mt = 0; mt < 2; mt++) {
                uint32_t off = ASW((uint32_t)((qm + mt*16 + (lane & 15)) * 128
                              + ks * 32 + ((lane >> 4) & 1) * 16));
                ldmx4(fQ[mt], sQ + off);
            }
            uint32_t fKh[8][2], fKl[8][2];
            #pragma unroll
            for (int np = 0; np < 4; np++) {
                uint32_t krow = kb*64 + np*16 + (lane & 7) + ((lane >> 4) & 1) * 8;
                uint32_t off = ASW(krow * 128 + ks * 32 + ((lane >> 3) & 1) * 16);
                uint32_t t[4];
                ldmx4(t, sKh + off);
                fKh[2*np][0] = t[0]; fKh[2*np][1] = t[1];
                fKh[2*np+1][0] = t[2]; fKh[2*np+1][1] = t[3];
                ldmx4(t, sKl + off);
                fKl[2*np][0] = t[0]; fKl[2*np][1] = t[1];
                fKl[2*np+1][0] = t[2]; fKl[2*np+1][1] = t[3];
            }
            #pragma unroll
            for (int mt = 0; mt < 2; mt++)
                #pragma unroll
                for (int nt = 0; nt < 8; nt++) {
                    mma_fp(S[mt][nt], fQ[mt], fKh[nt]);
                    mma_fp(S[mt][nt], fQ[mt], fKl[nt]);
                }
        }

        uint32_t pA[2][4][4];
        #pragma unroll
        for (int mt = 0; mt < 2; mt++) {
            #pragma unroll
            for (int nt = 0; nt < 8; nt++) {
                #pragma unroll
                for (int e = 0; e < 4; e++)
                    S[mt][nt][e] = softcap_p(S[mt][nt][e]);
                rsum[mt][0] += S[mt][nt][0] + S[mt][nt][1];
                rsum[mt][1] += S[mt][nt][2] + S[mt][nt][3];
            }
            #pragma unroll
            for (int kk = 0; kk < 4; kk++) {
                __half2 p0 = __floats2half2_rn(S[mt][2*kk][0],   S[mt][2*kk][1]);
                __half2 p1 = __floats2half2_rn(S[mt][2*kk][2],   S[mt][2*kk][3]);
                __half2 p2 = __floats2half2_rn(S[mt][2*kk+1][0], S[mt][2*kk+1][1]);
                __half2 p3 = __floats2half2_rn(S[mt][2*kk+1][2], S[mt][2*kk+1][3]);
                pA[mt][kk][0] = *(uint32_t*)&p0;
                pA[mt][kk][1] = *(uint32_t*)&p1;
                pA[mt][kk][2] = *(uint32_t*)&p2;
                pA[mt][kk][3] = *(uint32_t*)&p3;
            }
        }

        #pragma unroll
        for (int kk = 0; kk < 4; kk++) {
            uint32_t fVh[8][2], fVl[8][2];
            #pragma unroll
            for (int np = 0; np < 4; np++) {
                uint32_t vrow = kb*64 + kk*16 + (lane & 7) + ((lane >> 3) & 1) * 8;
                uint32_t off = ASW(vrow * 128 + (np*16 + ((lane >> 4) & 1) * 8) * 2);
                uint32_t t[4];
                ldmx4t(t, sVh + off);
                fVh[2*np][0] = t[0]; fVh[2*np][1] = t[1];
                fVh[2*np+1][0] = t[2]; fVh[2*np+1][1] = t[3];
                ldmx4t(t, sVl + off);
                fVl[2*np][0] = t[0]; fVl[2*np][1] = t[1];
                fVl[2*np+1][0] = t[2]; fVl[2*np+1][1] = t[3];
            }
            #pragma unroll
            for (int mt = 0; mt < 2; mt++)
                #pragma unroll
                for (int nt = 0; nt < 8; nt++) {
                    mma_fp(acc[mt][nt], pA[mt][kk], fVh[nt]);
                    mma_fp(acc[mt][nt], pA[mt][kk], fVl[nt]);
                }
        }
    }

    #pragma unroll
    for (int mt = 0; mt < 2; mt++) {
        rsum[mt][0] += __shfl_xor_sync(0xffffffffu, rsum[mt][0], 1);
        rsum[mt][0] += __shfl_xor_sync(0xffffffffu, rsum[mt][0], 2);
        rsum[mt][1] += __shfl_xor_sync(0xffffffffu, rsum[mt][1], 1);
        rsum[mt][1] += __shfl_xor_sync(0xffffffffu, rsum[mt][1], 2);
    }
    #pragma unroll
    for (int mt = 0; mt < 2; mt++) {
        const float inv0 = 1.0f / rsum[mt][0];
        const float inv1 = 1.0f / rsum[mt][1];
        #pragma unroll
        for (int nt = 0; nt < 8; nt++) {
            int rq_ = qm + mt*16 + (lane >> 2);
            int col = nt*8 + (lane & 3) * 2;
            size_t o0 = (size_t)(bt * SEQ + rq_) * GK + h * HD + col;
            size_t o1 = o0 + (size_t)8 * GK;
            *(__half2*)(g_a16 + o0) =
                __floats2half2_rn(acc[mt][nt][0] * inv0, acc[mt][nt][1] * inv0);
            *(__half2*)(g_a16 + o1) =
                __floats2half2_rn(acc[mt][nt][2] * inv1, acc[mt][nt][3] * inv1);
        }
    }
}

// ---------------------------------------------------------------------------
// launch
// ---------------------------------------------------------------------------
extern "C" void kernel_launch(void* const* d_in, const int* in_sizes, int n_in,
                              void* d_out, int out_size)
{
    const float* x  = (const float*)d_in[0];
    const float* Wq = (const float*)d_in[1];
    const float* Wk = (const float*)d_in[2];
    const float* Wv = (const float*)d_in[3];
    const float* Wo = (const float*)d_in[4];
    const float* qw = (const float*)d_in[5];
    const float* kw = (const float*)d_in[6];
    float* out = (float*)d_out;

    static __half *x16 = nullptr, *a16, *w1h, *w1l, *w2h;
    if (!x16) {
        cudaGetSymbolAddress((void**)&x16, g_x16);
        cudaGetSymbolAddress((void**)&a16, g_a16);
        cudaGetSymbolAddress((void**)&w1h, g_w1h);
        cudaGetSymbolAddress((void**)&w1l, g_w1l);
        cudaGetSymbolAddress((void**)&w2h, g_w2h);
        cudaFuncSetAttribute(attn_mma,
                             cudaFuncAttributeMaxDynamicSharedMemorySize, ATT_SMEM);
        cudaFuncSetAttribute((const void*)gemm_mma<1, 2>,
                             cudaFuncAttributeMaxDynamicSharedMemorySize, SMEM_G2);
        cudaFuncSetAttribute((const void*)gemm_mma<1, 1>,
                             cudaFuncAttributeMaxDynamicSharedMemorySize, SMEM_G1);
        cudaFuncSetAttribute((const void*)gemm_mma<0, 1>,
                             cudaFuncAttributeMaxDynamicSharedMemorySize, SMEM_G1);
    }

    const int n4 = MROWS * GK / 4;
    cvt_half<<<(n4 + 255) / 256, 256>>>(x, x16, n4);
    xpose_qkv<<<(QKVC * GK + 255) / 256, 256>>>(Wq, Wk, Wv, w1h, w1l);
    xpose_wo<<<(DIM * GK + 255) / 256, 256>>>(Wo, w2h);

    // Q projection: single-term fp16 weights (rmsnorm removes magnitude error)
    gemm_mma<1, 1><<<dim3(DIM / 128, MROWS / 128), 256, SMEM_G1>>>(
        x16, w1h, nullptr, nullptr, 0, qw, kw, 0);

    // K/V projection: 2-term fp16 weights
    gemm_mma<1, 2><<<dim3((QKVC - DIM) / 128, MROWS / 128), 256, SMEM_G2>>>(
        x16, w1h + (size_t)DIM * GK, w1l + (size_t)DIM * GK,
        nullptr, 0, qw, kw, DIM);

    attn_mma<<<dim3(NH, BTN), 256, ATT_SMEM>>>();

    gemm_mma<0, 1><<<dim3(DIM / 128, MROWS / 128), 256, SMEM_G1>>>(
        a16, w2h, nullptr, out, DIM, nullptr, nullptr, 0);
}

// round 17
// speedup vs baseline: 1.5217x; 1.0154x over previous
#include <cuda_runtime.h>
#include <cuda_bf16.h>
#include <cuda_fp16.h>
#include <math.h>
#include <stdint.h>

// Problem constants
#define BTN   128
#define SEQ   256
#define DIM   1024
#define NH    16
#define NKV   4
#define GRP   4
#define HD    64
#define MROWS (BTN*SEQ)      // 32768
#define QKVC  1536
#define GK    1024
#define EPSV  1e-6f
#define SCALEV 0.125f
#define CAPV  50.0f

// ---------------------------------------------------------------------------
// Scratch (device globals)
// ---------------------------------------------------------------------------
__device__ __align__(16) __half g_x16[(size_t)MROWS * GK];        // x as fp16
__device__ __align__(16) __half g_a16[(size_t)MROWS * GK];        // attn out fp16
__device__ __align__(16) __half g_w1h[(size_t)QKVC * GK];         // [n][k] hi
__device__ __align__(16) __half g_w1l[(size_t)QKVC * GK];         // [n][k] lo
__device__ __align__(16) __half g_w2h[(size_t)DIM * GK];          // Wo fp16 (single)
// attention tiles (fp16, single precision level)
__device__ __align__(16) __half g_qt16[(size_t)MROWS * GK];       // Q tiles
__device__ __align__(16) __half g_k16[(size_t)MROWS * 256];       // K tiles
__device__ __align__(16) __half g_v16[(size_t)MROWS * 256];       // V tiles

// ---------------------------------------------------------------------------
// helpers
// ---------------------------------------------------------------------------
__device__ __forceinline__ uint32_t smem_u32(const void* p) {
    uint32_t a;
    asm("{ .reg .u64 t; cvta.to.shared.u64 t, %1; cvt.u32.u64 %0, t; }"
        : "=r"(a) : "l"(p));
    return a;
}
__device__ __forceinline__ void cp16(uint32_t dst, const void* src) {
    asm volatile("cp.async.cg.shared.global [%0], [%1], 16;" :: "r"(dst), "l"(src));
}
__device__ __forceinline__ void ldmx4(uint32_t r[4], uint32_t addr) {
    asm volatile("ldmatrix.sync.aligned.m8n8.x4.shared.b16 {%0,%1,%2,%3}, [%4];"
                 : "=r"(r[0]), "=r"(r[1]), "=r"(r[2]), "=r"(r[3]) : "r"(addr));
}
__device__ __forceinline__ void ldmx4t(uint32_t r[4], uint32_t addr) {
    asm volatile("ldmatrix.sync.aligned.m8n8.x4.trans.shared.b16 {%0,%1,%2,%3}, [%4];"
                 : "=r"(r[0]), "=r"(r[1]), "=r"(r[2]), "=r"(r[3]) : "r"(addr));
}
__device__ __forceinline__ void mma_fp(float c[4], const uint32_t a[4],
                                       const uint32_t b[2]) {
    asm volatile("mma.sync.aligned.m16n8k16.row.col.f32.f16.f16.f32 "
                 "{%0,%1,%2,%3}, {%4,%5,%6,%7}, {%8,%9}, {%0,%1,%2,%3};"
                 : "+f"(c[0]), "+f"(c[1]), "+f"(c[2]), "+f"(c[3])
                 : "r"(a[0]), "r"(a[1]), "r"(a[2]), "r"(a[3]),
                   "r"(b[0]), "r"(b[1]));
}
__device__ __forceinline__ void split2h(float a, float b, uint32_t& H, uint32_t& L) {
    __half ah = __float2half_rn(a), bh = __float2half_rn(b);
    __half2 hh(ah, bh);
    H = *(uint32_t*)&hh;
    __half2 ll(__float2half_rn(a - __half2float(ah)),
               __float2half_rn(b - __half2float(bh)));
    L = *(uint32_t*)&ll;
}
// soft-capped softmax numerator, UNSHIFTED (constant cancels in normalization).
__device__ __forceinline__ float softcap_p(float y) {
    float u = y * y;
    float t = fmaf(u, fmaf(u, fmaf(u, -3.4540e-12f, 2.1333334e-8f),
                            -1.3333334e-4f), 1.0f);
    float arg = (y * t) * 1.44269504f;
    float p;
    asm("ex2.approx.ftz.f32 %0, %1;" : "=f"(p) : "f"(arg));
    return p;
}
#define ASW(o) ((o) ^ (((o) >> 3) & 0x70))

// ---------------------------------------------------------------------------
// conversions
// ---------------------------------------------------------------------------
__global__ void cvt_half(const float* __restrict__ in,
                         __half* __restrict__ out, int n4)
{
    int i = blockIdx.x * blockDim.x + threadIdx.x;
    if (i >= n4) return;
    float4 v = ((const float4*)in)[i];
    __half2* op = (__half2*)out;
    op[2*i]   = __floats2half2_rn(v.x, v.y);
    op[2*i+1] = __floats2half2_rn(v.z, v.w);
}

__global__ void xpose_qkv(const float* __restrict__ Wq, const float* __restrict__ Wk,
                          const float* __restrict__ Wv,
                          __half* __restrict__ th, __half* __restrict__ tl)
{
    size_t idx = (size_t)blockIdx.x * blockDim.x + threadIdx.x;
    if (idx >= (size_t)QKVC * GK) return;
    int k = (int)(idx & (GK - 1));
    int n = (int)(idx >> 10);
    float v;
    if (n < DIM)            v = Wq[(size_t)k * (NH*HD)  + n];
    else if (n < DIM + 256) v = Wk[(size_t)k * (NKV*HD) + (n - DIM)];
    else                    v = Wv[(size_t)k * (NKV*HD) + (n - DIM - 256)];
    __half hv = __float2half_rn(v);
    th[idx] = hv;
    tl[idx] = __float2half_rn(v - __half2float(hv));
}

__global__ void xpose_wo(const float* __restrict__ W,
                         __half* __restrict__ th)
{
    size_t idx = (size_t)blockIdx.x * blockDim.x + threadIdx.x;
    if (idx >= (size_t)DIM * GK) return;
    int k = (int)(idx & (GK - 1));
    int n = (int)(idx >> 10);
    th[idx] = __float2half_rn(W[(size_t)k * DIM + n]);
}

// ---------------------------------------------------------------------------
// fp16 GEMM: C[m,n] = A[m,:].(Bh[n,:][+Bl[n,:]]),  K=1024
// 128x128 CTA tile, 8 warps (32x64 warp tiles), BK=64, 2-stage, SW128.
// ---------------------------------------------------------------------------
#define BK      64
#define NCHUNK  (GK / BK)
#define TILE_B  (128 * 128)
#define OFF_A   0
#define OFF_BH  TILE_B
#define OFF_BL  (2*TILE_B)
#define SMEM_G2 (2 * 3 * TILE_B + 1024)
#define SMEM_G1 (2 * 2 * TILE_B + 1024)

template<int NB>
__device__ __forceinline__ void g_load(uint32_t sbase, int tid,
    const __half* A, const __half* Bh, const __half* Bl, int koff)
{
    #pragma unroll
    for (int it = 0; it < 4; it++) {
        int g = tid + it * 256;
        int row = g >> 3;
        int j   = g & 7;
        uint32_t dst = sbase + ASW((uint32_t)(row * 128 + j * 16));
        size_t so = (size_t)row * GK + koff + j * 8;
        cp16(dst + OFF_A,  A  + so);
        cp16(dst + OFF_BH, Bh + so);
        if (NB == 2) cp16(dst + OFF_BL, Bl + so);
    }
    asm volatile("cp.async.commit_group;" ::: "memory");
}

template<int EPI, int NB>
__global__ void __launch_bounds__(256, 2)
gemm_mma(const __half* __restrict__ a, const __half* __restrict__ bh,
         const __half* __restrict__ bl, float* __restrict__ C, int ldc,
         const float* __restrict__ qw, const float* __restrict__ kw, int gnoff)
{
    constexpr uint32_t STGX = (uint32_t)(1 + NB) * TILE_B;
    extern __shared__ char smem_raw[];
    uint32_t sbr = smem_u32(smem_raw);
    const uint32_t sb = (sbr + 1023) & ~1023u;
    const int tid  = threadIdx.x;
    const int wid  = tid >> 5;
    const int lane = tid & 31;
    const int bm = blockIdx.y * 128;
    const int bn = blockIdx.x * 128;

    const __half* A  = a  + (size_t)bm * GK;
    const __half* Bh = bh + (size_t)bn * GK;
    const __half* Bl = (NB == 2) ? bl + (size_t)bn * GK : nullptr;

    const int wm = (wid & 3) * 32;
    const int wn = (wid >> 2) * 64;
    const int ar = lane & 15;
    const int ac = (lane >> 4) * 16;
    const int br = (lane & 7) + ((lane >> 4) & 1) * 8;
    const int bc = ((lane >> 3) & 1) * 16;

    float acc[2][8][4];
    #pragma unroll
    for (int i = 0; i < 2; i++)
        #pragma unroll
        for (int j = 0; j < 8; j++)
            #pragma unroll
            for (int e = 0; e < 4; e++) acc[i][j][e] = 0.f;

    g_load<NB>(sb, tid, A, Bh, Bl, 0);

    for (int c = 0; c < NCHUNK; c++) {
        asm volatile("cp.async.wait_group 0;" ::: "memory");
        __syncthreads();
        if (c + 1 < NCHUNK)
            g_load<NB>(sb + ((c + 1) & 1) * STGX, tid, A, Bh, Bl, (c + 1) * BK);

        const uint32_t st = sb + (c & 1) * STGX;
        #pragma unroll
        for (int kk = 0; kk < 4; kk++) {
            const int kb = kk * 32;
            uint32_t fA[2][4];
            #pragma unroll
            for (int mt = 0; mt < 2; mt++) {
                uint32_t off = ASW((uint32_t)((wm + mt * 16 + ar) * 128 + kb + ac));
                ldmx4(fA[mt], st + OFF_A + off);
            }
            uint32_t fBh[8][2], fBl[8][2];
            #pragma unroll
            for (int g = 0; g < 4; g++) {
                uint32_t off = ASW((uint32_t)((wn + g * 16 + br) * 128 + kb + bc));
                uint32_t t[4];
                ldmx4(t, st + OFF_BH + off);
                fBh[2*g][0] = t[0]; fBh[2*g][1] = t[1];
                fBh[2*g+1][0] = t[2]; fBh[2*g+1][1] = t[3];
                if (NB == 2) {
                    ldmx4(t, st + OFF_BL + off);
                    fBl[2*g][0] = t[0]; fBl[2*g][1] = t[1];
                    fBl[2*g+1][0] = t[2]; fBl[2*g+1][1] = t[3];
                }
            }
            #pragma unroll
            for (int mt = 0; mt < 2; mt++)
                #pragma unroll
                for (int nt = 0; nt < 8; nt++) {
                    mma_fp(acc[mt][nt], fA[mt], fBh[nt]);
                    if (NB == 2) mma_fp(acc[mt][nt], fA[mt], fBl[nt]);
                }
        }
    }

    const int er = lane >> 2;
    const int ec = (lane & 3) * 2;

    if (EPI == 0) {
        #pragma unroll
        for (int mt = 0; mt < 2; mt++)
            #pragma unroll
            for (int nt = 0; nt < 8; nt++) {
                size_t row0 = (size_t)(bm + wm + mt * 16 + er) * ldc
                            + bn + wn + nt * 8 + ec;
                *(float2*)&C[row0]           = make_float2(acc[mt][nt][0], acc[mt][nt][1]);
                *(float2*)&C[row0 + 8 * ldc] = make_float2(acc[mt][nt][2], acc[mt][nt][3]);
            }
        return;
    }

    // ---- EPI == 1: QKV epilogue, rmsnorm fold + fp16 tile writes ----
    const int gn = gnoff + bn + wn;
    float wqk[16];
    if (gn < DIM) {
        #pragma unroll
        for (int nt = 0; nt < 8; nt++) {
            int col = nt * 8 + ec;
            wqk[2*nt]   = __ldg(&qw[col])   * __ldg(&kw[col]);
            wqk[2*nt+1] = __ldg(&qw[col+1]) * __ldg(&kw[col+1]);
        }
    }

    #pragma unroll
    for (int mt = 0; mt < 2; mt++) {
        #pragma unroll
        for (int hf = 0; hf < 2; hf++) {
            const int grow = bm + wm + mt * 16 + er + hf * 8;
            const int bt = grow >> 8;
            const int s  = grow & 255;
            float v[16];
            #pragma unroll
            for (int nt = 0; nt < 8; nt++) {
                v[2*nt]   = acc[mt][nt][hf*2];
                v[2*nt+1] = acc[mt][nt][hf*2+1];
            }
            if (gn < DIM) {                    // Q
                float ssq = 0.f;
                #pragma unroll
                for (int j = 0; j < 16; j++) ssq += v[j] * v[j];
                ssq += __shfl_xor_sync(0xffffffffu, ssq, 1);
                ssq += __shfl_xor_sync(0xffffffffu, ssq, 2);
                float r = rsqrtf(ssq * (1.0f / HD) + EPSV) * SCALEV;
                int h = gn >> 6;
                size_t dbase = ((size_t)(bt * NH + h) * SEQ + s) * HD;
                #pragma unroll
                for (int nt = 0; nt < 8; nt++) {
                    __half2 hp = __floats2half2_rn(v[2*nt] * r * wqk[2*nt],
                                                   v[2*nt+1] * r * wqk[2*nt+1]);
                    *(__half2*)(g_qt16 + dbase + nt * 8 + ec) = hp;
                }
            } else if (gn < DIM + 256) {       // K: rmsnorm, single fp16
                float ssq = 0.f;
                #pragma unroll
                for (int j = 0; j < 16; j++) ssq += v[j] * v[j];
                ssq += __shfl_xor_sync(0xffffffffu, ssq, 1);
                ssq += __shfl_xor_sync(0xffffffffu, ssq, 2);
                float r = rsqrtf(ssq * (1.0f / HD) + EPSV);
                int kvh = (gn - DIM) >> 6;
                size_t dbase = ((size_t)(bt * NKV + kvh) * SEQ + s) * HD;
                #pragma unroll
                for (int nt = 0; nt < 8; nt++) {
                    __half2 hp = __floats2half2_rn(v[2*nt] * r, v[2*nt+1] * r);
                    *(__half2*)(g_k16 + dbase + nt * 8 + ec) = hp;
                }
            } else {                            // V: single fp16
                int kvh = (gn - DIM - 256) >> 6;
                size_t dbase = ((size_t)(bt * NKV + kvh) * SEQ + s) * HD;
                #pragma unroll
                for (int nt = 0; nt < 8; nt++) {
                    __half2 hp = __floats2half2_rn(v[2*nt], v[2*nt+1]);
                    *(__half2*)(g_v16 + dbase + nt * 8 + ec) = hp;
                }
            }
        }
    }
}

// ---------------------------------------------------------------------------
// Tensor-core attention: block per (bt, h), 256 threads (8 warps).
// Q/K/V/P all single fp16 (fp32 accum). smem 96KB -> 2 CTAs/SM.
// ---------------------------------------------------------------------------
#define ATT_SMEM (3 * 32768 + 1024)

__global__ void __launch_bounds__(256, 2)
attn_mma()
{
    extern __shared__ char smem_raw[];
    uint32_t sbr = smem_u32(smem_raw);
    const uint32_t sb = (sbr + 1023) & ~1023u;
    const uint32_t sQ = sb, sK = sb + 32768, sV = sb + 65536;

    const int h  = blockIdx.x;
    const int bt = blockIdx.y;
    const int kvh = h >> 2;
    const int tid = threadIdx.x;
    const int lane = tid & 31;
    const int wid = tid >> 5;

    {
        const size_t qoff = (size_t)(bt * NH + h) * SEQ * HD;
        const size_t koff = (size_t)(bt * NKV + kvh) * SEQ * HD;
        const __half* srcs[3] = { g_qt16 + qoff, g_k16 + koff, g_v16 + koff };
        #pragma unroll
        for (int t = 0; t < 3; t++) {
            const __half* s = srcs[t];
            const uint32_t dtile = sb + t * 32768;
            #pragma unroll
            for (int i = 0; i < 8; i++) {
                uint32_t q = tid + i * 256;
                uint32_t row = q >> 3, j = q & 7;
                cp16(dtile + ASW(row * 128 + j * 16), s + row * 64 + j * 8);
            }
        }
        asm volatile("cp.async.commit_group;" ::: "memory");
        asm volatile("cp.async.wait_group 0;" ::: "memory");
    }
    __syncthreads();

    const int qm = wid * 32;
    float acc[2][8][4];
    float rsum[2][2];
    #pragma unroll
    for (int i = 0; i < 2; i++) {
        rsum[i][0] = rsum[i][1] = 0.f;
        #pragma unroll
        for (int j = 0; j < 8; j++)
            #pragma unroll
            for (int e = 0; e < 4; e++) acc[i][j][e] = 0.f;
    }

    for (int kb = 0; kb < 4; kb++) {
        float S[2][8][4];
        #pragma unroll
        for (int i = 0; i < 2; i++)
            #pragma unroll
            for (int j = 0; j < 8; j++)
                #pragma unroll
                for (int e = 0; e < 4; e++) S[i][j][e] = 0.f;

        #pragma unroll
        for (int ks = 0; ks < 4; ks++) {
            uint32_t fQ[2][4];
            #pragma unroll
            for (int mt = 0; mt < 2; mt++) {
                uint32_t off = ASW((uint32_t)((qm + mt*16 + (lane & 15)) * 128
                              + ks * 32 + ((lane >> 4) & 1) * 16));
                ldmx4(fQ[mt], sQ + off);
            }
            uint32_t fK[8][2];
            #pragma unroll
            for (int np = 0; np < 4; np++) {
                uint32_t krow = kb*64 + np*16 + (lane & 7) + ((lane >> 4) & 1) * 8;
                uint32_t off = ASW(krow * 128 + ks * 32 + ((lane >> 3) & 1) * 16);
                uint32_t t[4];
                ldmx4(t, sK + off);
                fK[2*np][0] = t[0]; fK[2*np][1] = t[1];
                fK[2*np+1][0] = t[2]; fK[2*np+1][1] = t[3];
            }
            #pragma unroll
            for (int mt = 0; mt < 2; mt++)
                #pragma unroll
                for (int nt = 0; nt < 8; nt++)
                    mma_fp(S[mt][nt], fQ[mt], fK[nt]);
        }

        uint32_t pA[2][4][4];
        #pragma unroll
        for (int mt = 0; mt < 2; mt++) {
            #pragma unroll
            for (int nt = 0; nt < 8; nt++) {
                #pragma unroll
                for (int e = 0; e < 4; e++)
                    S[mt][nt][e] = softcap_p(S[mt][nt][e]);
                rsum[mt][0] += S[mt][nt][0] + S[mt][nt][1];
                rsum[mt][1] += S[mt][nt][2] + S[mt][nt][3];
            }
            #pragma unroll
            for (int kk = 0; kk < 4; kk++) {
                __half2 p0 = __floats2half2_rn(S[mt][2*kk][0],   S[mt][2*kk][1]);
                __half2 p1 = __floats2half2_rn(S[mt][2*kk][2],   S[mt][2*kk][3]);
                __half2 p2 = __floats2half2_rn(S[mt][2*kk+1][0], S[mt][2*kk+1][1]);
                __half2 p3 = __floats2half2_rn(S[mt][2*kk+1][2], S[mt][2*kk+1][3]);
                pA[mt][kk][0] = *(uint32_t*)&p0;
                pA[mt][kk][1] = *(uint32_t*)&p1;
                pA[mt][kk][2] = *(uint32_t*)&p2;
                pA[mt][kk][3] = *(uint32_t*)&p3;
            }
        }

        #pragma unroll
        for (int kk = 0; kk < 4; kk++) {
            uint32_t fV[8][2];
            #pragma unroll
            for (int np = 0; np < 4; np++) {
                uint32_t vrow = kb*64 + kk*16 + (lane & 7) + ((lane >> 3) & 1) * 8;
                uint32_t off = ASW(vrow * 128 + (np*16 + ((lane >> 4) & 1) * 8) * 2);
                uint32_t t[4];
                ldmx4t(t, sV + off);
                fV[2*np][0] = t[0]; fV[2*np][1] = t[1];
                fV[2*np+1][0] = t[2]; fV[2*np+1][1] = t[3];
            }
            #pragma unroll
            for (int mt = 0; mt < 2; mt++)
                #pragma unroll
                for (int nt = 0; nt < 8; nt++)
                    mma_fp(acc[mt][nt], pA[mt][kk], fV[nt]);
        }
    }

    #pragma unroll
    for (int mt = 0; mt < 2; mt++) {
        rsum[mt][0] += __shfl_xor_sync(0xffffffffu, rsum[mt][0], 1);
        rsum[mt][0] += __shfl_xor_sync(0xffffffffu, rsum[mt][0], 2);
        rsum[mt][1] += __shfl_xor_sync(0xffffffffu, rsum[mt][1], 1);
        rsum[mt][1] += __shfl_xor_sync(0xffffffffu, rsum[mt][1], 2);
    }
    #pragma unroll
    for (int mt = 0; mt < 2; mt++) {
        const float inv0 = 1.0f / rsum[mt][0];
        const float inv1 = 1.0f / rsum[mt][1];
        #pragma unroll
        for (int nt = 0; nt < 8; nt++) {
            int rq_ = qm + mt*16 + (lane >> 2);
            int col = nt*8 + (lane & 3) * 2;
            size_t o0 = (size_t)(bt * SEQ + rq_) * GK + h * HD + col;
            size_t o1 = o0 + (size_t)8 * GK;
            *(__half2*)(g_a16 + o0) =
                __floats2half2_rn(acc[mt][nt][0] * inv0, acc[mt][nt][1] * inv0);
            *(__half2*)(g_a16 + o1) =
                __floats2half2_rn(acc[mt][nt][2] * inv1, acc[mt][nt][3] * inv1);
        }
    }
}

// ---------------------------------------------------------------------------
// launch
// ---------------------------------------------------------------------------
extern "C" void kernel_launch(void* const* d_in, const int* in_sizes, int n_in,
                              void* d_out, int out_size)
{
    const float* x  = (const float*)d_in[0];
    const float* Wq = (const float*)d_in[1];
    const float* Wk = (const float*)d_in[2];
    const float* Wv = (const float*)d_in[3];
    const float* Wo = (const float*)d_in[4];
    const float* qw = (const float*)d_in[5];
    const float* kw = (const float*)d_in[6];
    float* out = (float*)d_out;

    static __half *x16 = nullptr, *a16, *w1h, *w1l, *w2h;
    if (!x16) {
        cudaGetSymbolAddress((void**)&x16, g_x16);
        cudaGetSymbolAddress((void**)&a16, g_a16);
        cudaGetSymbolAddress((void**)&w1h, g_w1h);
        cudaGetSymbolAddress((void**)&w1l, g_w1l);
        cudaGetSymbolAddress((void**)&w2h, g_w2h);
        cudaFuncSetAttribute(attn_mma,
                             cudaFuncAttributeMaxDynamicSharedMemorySize, ATT_SMEM);
        cudaFuncSetAttribute((const void*)gemm_mma<1, 2>,
                             cudaFuncAttributeMaxDynamicSharedMemorySize, SMEM_G2);
        cudaFuncSetAttribute((const void*)gemm_mma<1, 1>,
                             cudaFuncAttributeMaxDynamicSharedMemorySize, SMEM_G1);
        cudaFuncSetAttribute((const void*)gemm_mma<0, 1>,
                             cudaFuncAttributeMaxDynamicSharedMemorySize, SMEM_G1);
    }

    const int n4 = MROWS * GK / 4;
    cvt_half<<<(n4 + 255) / 256, 256>>>(x, x16, n4);
    xpose_qkv<<<(QKVC * GK + 255) / 256, 256>>>(Wq, Wk, Wv, w1h, w1l);
    xpose_wo<<<(DIM * GK + 255) / 256, 256>>>(Wo, w2h);

    // Q projection: single-term fp16 weights
    gemm_mma<1, 1><<<dim3(DIM / 128, MROWS / 128), 256, SMEM_G1>>>(
        x16, w1h, nullptr, nullptr, 0, qw, kw, 0);

    // K/V projection: 2-term fp16 weights
    gemm_mma<1, 2><<<dim3((QKVC - DIM) / 128, MROWS / 128), 256, SMEM_G2>>>(
        x16, w1h + (size_t)DIM * GK, w1l + (size_t)DIM * GK,
        nullptr, 0, qw, kw, DIM);

    attn_mma<<<dim3(NH, BTN), 256, ATT_SMEM>>>();

    gemm_mma<0, 1><<<dim3(DIM / 128, MROWS / 128), 256, SMEM_G1>>>(
        a16, w2h, nullptr, out, DIM, nullptr, nullptr, 0);
}